// round 11
// baseline (speedup 1.0000x reference)
#include <cuda_runtime.h>
#include <math.h>
#include <stdint.h>

// Problem constants
#define Bb  4
#define Ss  2048
#define Dd  1024
#define Hh  16
#define HDd 64
#define Mm  (Bb*Ss)          // 8192

// Scratch (no allocation allowed -> __device__ globals)
__device__ __align__(16) float g_q[Bb*Hh*Ss*HDd];   // [B,H,S,HD] (tf32-rounded)
__device__ __align__(16) float g_k[Bb*Hh*Ss*HDd];   // (tf32-rounded)
__device__ __align__(16) float g_v[Bb*Hh*Ss*HDd];   // (tf32-rounded)
__device__ __align__(16) float g_o[Bb*Ss*Dd];       // [B,S,D] (tf32-rounded)
__device__ __align__(16) float g_xt[Mm*Dd];         // x rounded to tf32
__device__ __align__(16) float g_wt[4][Dd*Dd];      // wq,wk,wv,wo rounded

__device__ __forceinline__ uint32_t to_tf32(float f) {
    uint32_t u;
    asm("cvt.rna.tf32.f32 %0, %1;" : "=r"(u) : "f"(f));
    return u;
}

__device__ __forceinline__ void mma_tf32(float c[4],
                                         uint32_t a0, uint32_t a1, uint32_t a2, uint32_t a3,
                                         uint32_t b0, uint32_t b1) {
    asm volatile(
        "mma.sync.aligned.m16n8k8.row.col.f32.tf32.tf32.f32 "
        "{%0,%1,%2,%3}, {%4,%5,%6,%7}, {%8,%9}, {%0,%1,%2,%3};"
        : "+f"(c[0]), "+f"(c[1]), "+f"(c[2]), "+f"(c[3])
        : "r"(a0), "r"(a1), "r"(a2), "r"(a3), "r"(b0), "r"(b1));
}

__device__ __forceinline__ void cp16(void* dst_smem, const void* src) {
    uint32_t d = (uint32_t)__cvta_generic_to_shared(dst_smem);
    asm volatile("cp.async.cg.shared.global [%0], [%1], 16;\n" :: "r"(d), "l"(src));
}
#define CP_COMMIT() asm volatile("cp.async.commit_group;\n" ::: "memory")
#define CP_WAIT1()  asm volatile("cp.async.wait_group 1;\n" ::: "memory")
#define CP_WAIT0()  asm volatile("cp.async.wait_group 0;\n" ::: "memory")

// ---------------------------------------------------------------------------
// Pre-pass: round x and the 4 weight matrices to tf32 (cvt.rna), once.
// ---------------------------------------------------------------------------
__global__ __launch_bounds__(256)
void round_all(const float* __restrict__ x,
               const float* __restrict__ wq, const float* __restrict__ wk,
               const float* __restrict__ wv, const float* __restrict__ wo)
{
    const int bid = blockIdx.x;
    const float* src; float* dst; size_t base;
    if (bid < 8192) { src = x; dst = g_xt; base = (size_t)bid * 1024; }
    else {
        const int w = (bid - 8192) >> 10;           // 0..3
        const int wb = (bid - 8192) & 1023;
        src = (w == 0) ? wq : (w == 1) ? wk : (w == 2) ? wv : wo;
        dst = g_wt[w]; base = (size_t)wb * 1024;
    }
    const size_t i = base + threadIdx.x * 4;
    float4 v = *(const float4*)(src + i);
    uint4 r = make_uint4(to_tf32(v.x), to_tf32(v.y), to_tf32(v.z), to_tf32(v.w));
    *(uint4*)(dst + i) = r;
}

// ---------------------------------------------------------------------------
// tf32 tensor-core GEMM, 3-stage cp.async pipeline, no cvt in mainloop
// (inputs pre-rounded; raw bits fed to mma).  [unchanged from R9]
// QKV=true:  grid (24,64). blockIdx.x>>3 selects Q/K/V; A=g_xt, W=g_wt[sel],
//            out = g_q/g_k/g_v head-split [B,H,S,HD], values tf32-rounded.
// QKV=false: grid (8,64). A=g_o (pre-rounded by flash), W=g_wt[3], out=d_out.
// ---------------------------------------------------------------------------
#define AP 20
#define BP 136
#define ASZ (128*AP)
#define BSZ (16*BP)
#define GEMM_SMEM (3*(ASZ+BSZ)*4)    // 56832 bytes

template<bool QKV>
__global__ __launch_bounds__(256, 2)
void tc_gemm(const float* __restrict__ bq, const float* __restrict__ bk,
             const float* __restrict__ bv, const float* __restrict__ bo,
             float* __restrict__ out_param)
{
    const int K = Dd, N = Dd;
    extern __shared__ float dsm[];
    float* Abuf = dsm;
    float* Bbuf = dsm + 3 * ASZ;

    int sel; const float* A; const float* W; const float* bias; float* outp;
    int bnx;
    if (QKV) {
        sel = blockIdx.x >> 3;  bnx = blockIdx.x & 7;
        A = g_xt;  W = g_wt[sel];
        bias = (sel == 0) ? bq : (sel == 1) ? bk : bv;
        outp = (sel == 0) ? g_q : (sel == 1) ? g_k : g_v;
    } else {
        sel = 3; bnx = blockIdx.x;
        A = g_o;  W = g_wt[3];  bias = bo;  outp = out_param;
    }

    const int t    = threadIdx.x;
    const int lane = t & 31;
    const int wid  = t >> 5;
    const int wm   = (wid & 3) * 32;
    const int wn   = (wid >> 2) * 64;
    const int g    = lane >> 2;
    const int tig  = lane & 3;

    const int bm = blockIdx.y * 128;
    const int bn = bnx * 128;

    const int ar = t >> 2;
    const int akc = (t & 3) * 4;
    const int brr = t >> 5;
    const int bcc = (t & 31) * 4;

    const float* Arow0 = A + (size_t)(bm + ar) * K + akc;
    const float* Arow1 = A + (size_t)(bm + ar + 64) * K + akc;
    const float* Wrow0 = W + (size_t)brr * N + bn + bcc;
    const float* Wrow1 = W + (size_t)(brr + 8) * N + bn + bcc;

    const int NT = K / 16;

    auto issue = [&](int kt, int stg) {
        if (kt < NT) {
            const int k0 = kt * 16;
            float* Asg = Abuf + stg * ASZ;
            float* Bsg = Bbuf + stg * BSZ;
            cp16(Asg + ar * AP + akc,        Arow0 + k0);
            cp16(Asg + (ar + 64) * AP + akc, Arow1 + k0);
            cp16(Bsg + brr * BP + bcc,       Wrow0 + (size_t)k0 * N);
            cp16(Bsg + (brr + 8) * BP + bcc, Wrow1 + (size_t)k0 * N);
        }
        CP_COMMIT();
    };

    float acc[2][8][4];
    #pragma unroll
    for (int ma = 0; ma < 2; ma++)
        #pragma unroll
        for (int na = 0; na < 8; na++)
            #pragma unroll
            for (int i = 0; i < 4; i++) acc[ma][na][i] = 0.f;

    issue(0, 0);
    issue(1, 1);

    for (int kt = 0; kt < NT; kt++) {
        const int cur = kt % 3;
        CP_WAIT1();
        __syncthreads();
        issue(kt + 2, (kt + 2) % 3);

        const uint32_t* Asg = (const uint32_t*)(Abuf + cur * ASZ);
        const uint32_t* Bsg = (const uint32_t*)(Bbuf + cur * BSZ);

        #pragma unroll
        for (int ks = 0; ks < 16; ks += 8) {
            uint32_t a[2][4];
            #pragma unroll
            for (int ma = 0; ma < 2; ma++) {
                const int m0 = wm + ma * 16 + g;
                a[ma][0] = Asg[(m0    ) * AP + ks + tig    ];
                a[ma][1] = Asg[(m0 + 8) * AP + ks + tig    ];
                a[ma][2] = Asg[(m0    ) * AP + ks + tig + 4];
                a[ma][3] = Asg[(m0 + 8) * AP + ks + tig + 4];
            }
            #pragma unroll
            for (int na = 0; na < 8; na++) {
                const int n0 = wn + na * 8 + g;
                uint32_t b0 = Bsg[(ks + tig    ) * BP + n0];
                uint32_t b1 = Bsg[(ks + tig + 4) * BP + n0];
                #pragma unroll
                for (int ma = 0; ma < 2; ma++)
                    mma_tf32(acc[ma][na], a[ma][0], a[ma][1], a[ma][2], a[ma][3], b0, b1);
            }
        }
    }

    #pragma unroll
    for (int ma = 0; ma < 2; ma++) {
        #pragma unroll
        for (int na = 0; na < 8; na++) {
            const int row0 = bm + wm + ma * 16 + g;
            const int col  = bn + wn + na * 8 + tig * 2;
            const float bia0 = bias[col], bia1 = bias[col + 1];
            #pragma unroll
            for (int half = 0; half < 2; half++) {
                const int mrow = row0 + half * 8;
                const float v0 = acc[ma][na][half * 2 + 0] + bia0;
                const float v1 = acc[ma][na][half * 2 + 1] + bia1;
                if (QKV) {
                    const int b = mrow / Ss, s = mrow % Ss;
                    const int h = col / HDd, d = col % HDd;
                    uint2 r = make_uint2(to_tf32(v0), to_tf32(v1));
                    *(uint2*)&outp[(((size_t)b * Hh + h) * Ss + s) * HDd + d] = r;
                } else {
                    *(float2*)&outp[(size_t)mrow * Dd + col] = make_float2(v0, v1);
                }
            }
        }
    }
}

// ---------------------------------------------------------------------------
// Tensor-core flash attention (causal), tf32 mma, FA2-style.
// R11: q-tile 128 rows per CTA (8 warps, 256 threads) — halves total K/V
// traffic vs 64-row tiles. K/V cp.async double-buffered. blockIdx.x reversed
// so heavy (late-q) blocks schedule first. Lower-half warps waste one fully-
// masked tile (contributes exactly zero — numerics identical to R9).
// ---------------------------------------------------------------------------
#define KP 68
#define VP 72
#define PP 68
#define KSZ (64*KP)
#define VSZ (64*VP)
#define FA_SMEM ((2*KSZ + 2*VSZ + 8*16*PP) * 4)   // 106496 bytes

__global__ __launch_bounds__(256)
void flash_attn_tc()
{
    extern __shared__ uint32_t dsmu[];
    uint32_t* Ks = dsmu;                       // [2][64][KP]
    uint32_t* Vs = dsmu + 2 * KSZ;             // [2][64][VP]
    uint32_t* Ps = dsmu + 2 * KSZ + 2 * VSZ;   // [8][16][PP]

    const int tid  = threadIdx.x;
    const int lane = tid & 31;
    const int wid  = tid >> 5;                 // 0..7
    const int g    = lane >> 2;
    const int tig  = lane & 3;
    const int q0   = (int)(gridDim.x - 1 - blockIdx.x) * 128;
    const int bh   = blockIdx.y;
    const int qr0  = q0 + wid * 16;

    const float* qb = g_q + (size_t)bh * Ss * HDd;
    const float* kb = g_k + (size_t)bh * Ss * HDd;
    const float* vb = g_v + (size_t)bh * Ss * HDd;

    // q pre-rounded; *0.125 exact (power of 2) -> bits remain valid tf32
    uint32_t qf[8][4];
    #pragma unroll
    for (int c = 0; c < 8; c++) {
        qf[c][0] = __float_as_uint(qb[(size_t)(qr0 + g    ) * HDd + c * 8 + tig    ] * 0.125f);
        qf[c][1] = __float_as_uint(qb[(size_t)(qr0 + g + 8) * HDd + c * 8 + tig    ] * 0.125f);
        qf[c][2] = __float_as_uint(qb[(size_t)(qr0 + g    ) * HDd + c * 8 + tig + 4] * 0.125f);
        qf[c][3] = __float_as_uint(qb[(size_t)(qr0 + g + 8) * HDd + c * 8 + tig + 4] * 0.125f);
    }

    float acc[8][4];
    #pragma unroll
    for (int na = 0; na < 8; na++)
        #pragma unroll
        for (int i = 0; i < 4; i++) acc[na][i] = 0.f;

    float m_lo = -INFINITY, m_hi = -INFINITY;
    float l_lo = 0.f, l_hi = 0.f;

    uint32_t* Pw = Ps + wid * 16 * PP;
    const int nt = q0 / 64 + 2;               // key tiles covering rows q0..q0+127

    auto issue_tile = [&](int kt, int buf) {
        const float* ksrc = kb + (size_t)kt * 64 * HDd;
        const float* vsrc = vb + (size_t)kt * 64 * HDd;
        uint32_t* Kd = Ks + buf * KSZ;
        uint32_t* Vd = Vs + buf * VSZ;
        #pragma unroll
        for (int i = 0; i < 4; i++) {
            const int idx = tid + i * 256;    // 1024 float4 chunks each
            const int row = idx >> 4;
            const int c4  = (idx & 15) * 4;
            cp16(&Kd[row * KP + c4], ksrc + row * HDd + c4);
            cp16(&Vd[row * VP + c4], vsrc + row * HDd + c4);
        }
        CP_COMMIT();
    };

    issue_tile(0, 0);

    for (int kt = 0; kt < nt; kt++) {
        const int cur = kt & 1;
        CP_WAIT0();
        __syncthreads();
        if (kt + 1 < nt) issue_tile(kt + 1, cur ^ 1);

        const uint32_t* Kc = Ks + cur * KSZ;
        const uint32_t* Vc = Vs + cur * VSZ;

        float s[8][4];
        #pragma unroll
        for (int na = 0; na < 8; na++)
            #pragma unroll
            for (int i = 0; i < 4; i++) s[na][i] = 0.f;

        #pragma unroll
        for (int c = 0; c < 8; c++) {
            #pragma unroll
            for (int na = 0; na < 8; na++) {
                uint32_t b0 = Kc[(na * 8 + g) * KP + c * 8 + tig    ];
                uint32_t b1 = Kc[(na * 8 + g) * KP + c * 8 + tig + 4];
                mma_tf32(s[na], qf[c][0], qf[c][1], qf[c][2], qf[c][3], b0, b1);
            }
        }

        // causal mask: needed only when this tile reaches past this warp's rows
        if (kt * 64 + 63 > qr0) {
            const int rlo = qr0 + g, rhi = qr0 + g + 8;
            #pragma unroll
            for (int na = 0; na < 8; na++) {
                const int c0 = kt * 64 + na * 8 + tig * 2;
                const int c1 = c0 + 1;
                if (c0 > rlo) s[na][0] = -INFINITY;
                if (c1 > rlo) s[na][1] = -INFINITY;
                if (c0 > rhi) s[na][2] = -INFINITY;
                if (c1 > rhi) s[na][3] = -INFINITY;
            }
        }

        float tm_lo = -INFINITY, tm_hi = -INFINITY;
        #pragma unroll
        for (int na = 0; na < 8; na++) {
            tm_lo = fmaxf(tm_lo, fmaxf(s[na][0], s[na][1]));
            tm_hi = fmaxf(tm_hi, fmaxf(s[na][2], s[na][3]));
        }
        tm_lo = fmaxf(tm_lo, __shfl_xor_sync(0xffffffffu, tm_lo, 1));
        tm_lo = fmaxf(tm_lo, __shfl_xor_sync(0xffffffffu, tm_lo, 2));
        tm_hi = fmaxf(tm_hi, __shfl_xor_sync(0xffffffffu, tm_hi, 1));
        tm_hi = fmaxf(tm_hi, __shfl_xor_sync(0xffffffffu, tm_hi, 2));

        const float mn_lo = fmaxf(m_lo, tm_lo);
        const float mn_hi = fmaxf(m_hi, tm_hi);
        const float sc_lo = __expf(m_lo - mn_lo);
        const float sc_hi = __expf(m_hi - mn_hi);

        float sum_lo = 0.f, sum_hi = 0.f;
        #pragma unroll
        for (int na = 0; na < 8; na++) {
            s[na][0] = __expf(s[na][0] - mn_lo);
            s[na][1] = __expf(s[na][1] - mn_lo);
            s[na][2] = __expf(s[na][2] - mn_hi);
            s[na][3] = __expf(s[na][3] - mn_hi);
            sum_lo += s[na][0] + s[na][1];
            sum_hi += s[na][2] + s[na][3];
        }
        sum_lo += __shfl_xor_sync(0xffffffffu, sum_lo, 1);
        sum_lo += __shfl_xor_sync(0xffffffffu, sum_lo, 2);
        sum_hi += __shfl_xor_sync(0xffffffffu, sum_hi, 1);
        sum_hi += __shfl_xor_sync(0xffffffffu, sum_hi, 2);

        l_lo = l_lo * sc_lo + sum_lo;  m_lo = mn_lo;
        l_hi = l_hi * sc_hi + sum_hi;  m_hi = mn_hi;

        #pragma unroll
        for (int na = 0; na < 8; na++) {
            acc[na][0] *= sc_lo; acc[na][1] *= sc_lo;
            acc[na][2] *= sc_hi; acc[na][3] *= sc_hi;
        }

        #pragma unroll
        for (int na = 0; na < 8; na++) {
            uint2 plo = make_uint2(to_tf32(s[na][0]), to_tf32(s[na][1]));
            uint2 phi = make_uint2(to_tf32(s[na][2]), to_tf32(s[na][3]));
            *(uint2*)&Pw[(g    ) * PP + na * 8 + tig * 2] = plo;
            *(uint2*)&Pw[(g + 8) * PP + na * 8 + tig * 2] = phi;
        }
        __syncwarp();

        #pragma unroll
        for (int c = 0; c < 8; c++) {
            uint32_t a0 = Pw[(g    ) * PP + c * 8 + tig    ];
            uint32_t a1 = Pw[(g + 8) * PP + c * 8 + tig    ];
            uint32_t a2 = Pw[(g    ) * PP + c * 8 + tig + 4];
            uint32_t a3 = Pw[(g + 8) * PP + c * 8 + tig + 4];
            #pragma unroll
            for (int na = 0; na < 8; na++) {
                uint32_t b0 = Vc[(c * 8 + tig    ) * VP + na * 8 + g];
                uint32_t b1 = Vc[(c * 8 + tig + 4) * VP + na * 8 + g];
                mma_tf32(acc[na], a0, a1, a2, a3, b0, b1);
            }
        }
    }

    // epilogue: normalize, round to tf32 (feeds O-GEMM A operand), write
    const float inv_lo = 1.f / l_lo;
    const float inv_hi = 1.f / l_hi;
    const int b = bh / Hh, h = bh % Hh;
    float* olo = g_o + ((size_t)b * Ss + (qr0 + g    )) * Dd + h * HDd;
    float* ohi = g_o + ((size_t)b * Ss + (qr0 + g + 8)) * Dd + h * HDd;
    #pragma unroll
    for (int na = 0; na < 8; na++) {
        uint2 vlo = make_uint2(to_tf32(acc[na][0] * inv_lo), to_tf32(acc[na][1] * inv_lo));
        uint2 vhi = make_uint2(to_tf32(acc[na][2] * inv_hi), to_tf32(acc[na][3] * inv_hi));
        *(uint2*)&olo[na * 8 + tig * 2] = vlo;
        *(uint2*)&ohi[na * 8 + tig * 2] = vhi;
    }
}

// ---------------------------------------------------------------------------
extern "C" void kernel_launch(void* const* d_in, const int* in_sizes, int n_in,
                              void* d_out, int out_size)
{
    const float* x  = (const float*)d_in[0];
    const float* wq = (const float*)d_in[1];
    const float* bq = (const float*)d_in[2];
    const float* wk = (const float*)d_in[3];
    const float* bk = (const float*)d_in[4];
    const float* wv = (const float*)d_in[5];
    const float* bv = (const float*)d_in[6];
    const float* wo = (const float*)d_in[7];
    const float* bo = (const float*)d_in[8];
    float* out = (float*)d_out;

    cudaFuncSetAttribute(tc_gemm<true>,  cudaFuncAttributeMaxDynamicSharedMemorySize, GEMM_SMEM);
    cudaFuncSetAttribute(tc_gemm<false>, cudaFuncAttributeMaxDynamicSharedMemorySize, GEMM_SMEM);
    cudaFuncSetAttribute(flash_attn_tc,  cudaFuncAttributeMaxDynamicSharedMemorySize, FA_SMEM);

    // pre-round x + weights to tf32
    round_all<<<8192 + 4 * 1024, 256>>>(x, wq, wk, wv, wo);

    // fused QKV projection
    dim3 qgrid(24, Mm / 128);             // (24, 64)
    tc_gemm<true><<<qgrid, 256, GEMM_SMEM>>>(bq, bk, bv, nullptr, nullptr);

    // attention: 128-row q tiles
    dim3 agrid(Ss / 128, Bb * Hh);        // (16, 64)
    flash_attn_tc<<<agrid, 256, FA_SMEM>>>();

    // output projection
    dim3 ogrid(8, Mm / 128);              // (8, 64)
    tc_gemm<false><<<ogrid, 256, GEMM_SMEM>>>(nullptr, nullptr, nullptr, bo, out);
}

// round 12
// speedup vs baseline: 1.6150x; 1.6150x over previous
#include <cuda_runtime.h>
#include <cuda_fp16.h>
#include <math.h>
#include <stdint.h>

// Problem constants
#define Bb  4
#define Ss  2048
#define Dd  1024
#define Hh  16
#define HDd 64
#define Mm  (Bb*Ss)          // 8192

// Scratch (no allocation allowed -> __device__ globals). All fp16.
__device__ __align__(16) __half g_q [Bb*Hh*Ss*HDd];  // [B,H,S,HD], pre-scaled by 0.125
__device__ __align__(16) __half g_k [Bb*Hh*Ss*HDd];  // [B,H,S,HD]
__device__ __align__(16) __half g_vT[Bb*Hh*HDd*Ss];  // [B,H,HD,S]  (transposed!)
__device__ __align__(16) __half g_o [Bb*Ss*Dd];      // [B,S,D]
__device__ __align__(16) __half g_xt[Mm*Dd];         // x -> fp16 [M,K]
__device__ __align__(16) __half g_wt[4][Dd*Dd];      // weights TRANSPOSED [N,K], fp16

__device__ __forceinline__ uint32_t pack_h2(float lo, float hi) {
    __half2 h = __float22half2_rn(make_float2(lo, hi));
    return *(uint32_t*)&h;
}

__device__ __forceinline__ void mma_f16(float c[4],
                                        uint32_t a0, uint32_t a1, uint32_t a2, uint32_t a3,
                                        uint32_t b0, uint32_t b1) {
    asm volatile(
        "mma.sync.aligned.m16n8k16.row.col.f32.f16.f16.f32 "
        "{%0,%1,%2,%3}, {%4,%5,%6,%7}, {%8,%9}, {%0,%1,%2,%3};"
        : "+f"(c[0]), "+f"(c[1]), "+f"(c[2]), "+f"(c[3])
        : "r"(a0), "r"(a1), "r"(a2), "r"(a3), "r"(b0), "r"(b1));
}

__device__ __forceinline__ void cp16(void* dst_smem, const void* src) {
    uint32_t d = (uint32_t)__cvta_generic_to_shared(dst_smem);
    asm volatile("cp.async.cg.shared.global [%0], [%1], 16;\n" :: "r"(d), "l"(src));
}
#define CP_COMMIT() asm volatile("cp.async.commit_group;\n" ::: "memory")
#define CP_WAIT1()  asm volatile("cp.async.wait_group 1;\n" ::: "memory")
#define CP_WAIT0()  asm volatile("cp.async.wait_group 0;\n" ::: "memory")

// ---------------------------------------------------------------------------
// Pre-pass 1: x (fp32) -> g_xt (fp16). 8 elems/thread.
// ---------------------------------------------------------------------------
__global__ __launch_bounds__(256)
void round_x(const float* __restrict__ x)
{
    const size_t i = ((size_t)blockIdx.x * 256 + threadIdx.x) * 8;
    float4 v0 = *(const float4*)(x + i);
    float4 v1 = *(const float4*)(x + i + 4);
    uint4 u;
    u.x = pack_h2(v0.x, v0.y);  u.y = pack_h2(v0.z, v0.w);
    u.z = pack_h2(v1.x, v1.y);  u.w = pack_h2(v1.z, v1.w);
    *(uint4*)(g_xt + i) = u;
}

// ---------------------------------------------------------------------------
// Pre-pass 2: transpose + convert weights: W[k][n] fp32 -> g_wt[w][n][k] fp16
// grid (32,32,4), block 256 (=32x8)
// ---------------------------------------------------------------------------
__global__ __launch_bounds__(256)
void transpose_w(const float* __restrict__ wq, const float* __restrict__ wk,
                 const float* __restrict__ wv, const float* __restrict__ wo)
{
    __shared__ float sm[32][33];
    const int w = blockIdx.z;
    const float* src = (w == 0) ? wq : (w == 1) ? wk : (w == 2) ? wv : wo;
    __half* dst = g_wt[w];
    const int k0 = blockIdx.x * 32, n0 = blockIdx.y * 32;
    const int tx = threadIdx.x & 31, ty = threadIdx.x >> 5;
    #pragma unroll
    for (int i = 0; i < 4; i++)
        sm[ty + 8 * i][tx] = src[(size_t)(k0 + ty + 8 * i) * Dd + n0 + tx];
    __syncthreads();
    #pragma unroll
    for (int i = 0; i < 4; i++)
        dst[(size_t)(n0 + ty + 8 * i) * Dd + k0 + tx] = __float2half(sm[tx][ty + 8 * i]);
}

// ---------------------------------------------------------------------------
// fp16 tensor-core GEMM (m16n8k16), 3-stage cp.async ring, k-tile 32.
// A [M,K] k-major fp16 (g_xt or g_o); B = g_wt[sel] [N,K] k-major fp16.
// Block tile 128x128, 8 warps (warp 32m x 64n): 2 m-atoms x 8 n-atoms.
// smem pitch PA=20 words per row (32 halves data + pad; 20 mod 32 = 20,
// g*20 mod 32 spans {0,4,..,28} -> conflict-free fragment gathers).
// QKV=true: grid (24,64): x>>3 = sel(Q/K/V), x&7 = n-block.
//   Q: *0.125, head-split [B,H,S,HD]; K: head-split; V: transposed [B,H,HD,S].
// QKV=false: grid (8,64): O projection -> d_out fp32.
// ---------------------------------------------------------------------------
#define PA 20
#define ROWW (PA)                 // words per row
#define ASTG (128*PA)             // words per A stage (2560)
#define STGW (2*ASTG)             // words per stage A+B (5120 = 20480B)
#define GEMM_SMEM (3*STGW*4)      // 61440 bytes

template<bool QKV>
__global__ __launch_bounds__(256, 2)
void tc_gemm(const float* __restrict__ bq, const float* __restrict__ bk,
             const float* __restrict__ bv, const float* __restrict__ bo,
             float* __restrict__ out_param)
{
    extern __shared__ uint32_t dsw[];

    int sel; const __half* A; const __half* W; const float* bias;
    int bnx;
    if (QKV) {
        sel = blockIdx.x >> 3;  bnx = blockIdx.x & 7;
        A = g_xt;  W = g_wt[sel];
        bias = (sel == 0) ? bq : (sel == 1) ? bk : bv;
    } else {
        sel = 3; bnx = blockIdx.x;
        A = g_o;  W = g_wt[3];  bias = bo;
    }

    const int t    = threadIdx.x;
    const int lane = t & 31;
    const int wid  = t >> 5;
    const int wm   = (wid & 3) * 32;
    const int wn   = (wid >> 2) * 64;
    const int g    = lane >> 2;
    const int tig  = lane & 3;

    const int bm = blockIdx.y * 128;
    const int bn = bnx * 128;

    // loader: thread -> row r = t>>1 (0..127), cp = t&1 -> 2 chunks of 8 halves
    const int lr = t >> 1;
    const int lcp = t & 1;
    const __half* Arow = A + (size_t)(bm + lr) * Dd + lcp * 16;
    const __half* Wrow = W + (size_t)(bn + lr) * Dd + lcp * 16;

    const int NT = Dd / 32;   // 32 k-tiles

    auto issue = [&](int kt, int stg) {
        if (kt < NT) {
            const int k0 = kt * 32;
            uint32_t* Aw = dsw + stg * STGW;
            uint32_t* Bw = Aw + ASTG;
            cp16(Aw + lr * ROWW + lcp * 8,     Arow + k0);
            cp16(Aw + lr * ROWW + lcp * 8 + 4, Arow + k0 + 8);
            cp16(Bw + lr * ROWW + lcp * 8,     Wrow + k0);
            cp16(Bw + lr * ROWW + lcp * 8 + 4, Wrow + k0 + 8);
        }
        CP_COMMIT();
    };

    float acc[2][8][4];
    #pragma unroll
    for (int ma = 0; ma < 2; ma++)
        #pragma unroll
        for (int na = 0; na < 8; na++)
            #pragma unroll
            for (int i = 0; i < 4; i++) acc[ma][na][i] = 0.f;

    issue(0, 0);
    issue(1, 1);

    for (int kt = 0; kt < NT; kt++) {
        const int cur = kt % 3;
        CP_WAIT1();
        __syncthreads();
        issue(kt + 2, (kt + 2) % 3);

        const uint32_t* Aw = dsw + cur * STGW;
        const uint32_t* Bw = Aw + ASTG;

        #pragma unroll
        for (int ks = 0; ks < 2; ks++) {          // two k16 chunks
            const int kw = ks * 8;                // word offset
            uint32_t a[2][4];
            #pragma unroll
            for (int ma = 0; ma < 2; ma++) {
                const int r0 = wm + ma * 16 + g;
                a[ma][0] = Aw[(r0    ) * ROWW + kw + tig    ];
                a[ma][1] = Aw[(r0 + 8) * ROWW + kw + tig    ];
                a[ma][2] = Aw[(r0    ) * ROWW + kw + tig + 4];
                a[ma][3] = Aw[(r0 + 8) * ROWW + kw + tig + 4];
            }
            #pragma unroll
            for (int na = 0; na < 8; na++) {
                const int n0 = wn + na * 8 + g;
                uint32_t b0 = Bw[n0 * ROWW + kw + tig    ];
                uint32_t b1 = Bw[n0 * ROWW + kw + tig + 4];
                #pragma unroll
                for (int ma = 0; ma < 2; ma++)
                    mma_f16(acc[ma][na], a[ma][0], a[ma][1], a[ma][2], a[ma][3], b0, b1);
            }
        }
    }

    // ---- epilogue ----
    #pragma unroll
    for (int ma = 0; ma < 2; ma++) {
        #pragma unroll
        for (int na = 0; na < 8; na++) {
            const int row0 = bm + wm + ma * 16 + g;
            const int col  = bn + wn + na * 8 + tig * 2;
            const float bia0 = bias[col], bia1 = bias[col + 1];
            #pragma unroll
            for (int half_i = 0; half_i < 2; half_i++) {
                const int mrow = row0 + half_i * 8;
                float v0 = acc[ma][na][half_i * 2 + 0] + bia0;
                float v1 = acc[ma][na][half_i * 2 + 1] + bia1;
                if (QKV) {
                    const int b = mrow / Ss, s = mrow % Ss;
                    const int h = col / HDd, d = col % HDd;
                    if (sel == 0) { v0 *= 0.125f; v1 *= 0.125f; }
                    if (sel == 2) {
                        // V: transposed store [B,H,HD,S]
                        __half* dst = g_vT + (((size_t)b * Hh + h) * HDd) * Ss + s;
                        dst[(size_t)d * Ss]       = __float2half(v0);
                        dst[(size_t)(d + 1) * Ss] = __float2half(v1);
                    } else {
                        __half* dst = (sel == 0) ? g_q : g_k;
                        *(uint32_t*)&dst[(((size_t)b * Hh + h) * Ss + s) * HDd + d] =
                            pack_h2(v0, v1);
                    }
                } else {
                    *(float2*)&out_param[(size_t)mrow * Dd + col] = make_float2(v0, v1);
                }
            }
        }
    }
}

// ---------------------------------------------------------------------------
// fp16 tensor-core flash attention (causal), m16n8k16, FA2-style.
// Block: 4 warps, 64 q-rows. K tile [64 key][64 hd], V tile [64 hd][64 key]
// (from g_vT), both pitch 36 words (conflict-free). Double-buffered cp.async.
// P never touches smem: QK C-fragments repack directly into PV A-fragments.
// ---------------------------------------------------------------------------
#define FP 36                         // words per smem row
#define TSZ (64*FP)                   // words per tile (2304)
#define FA_SMEM (4*TSZ*4)             // K x2 + V x2 = 36864 bytes

__global__ __launch_bounds__(128)
void flash_attn_tc()
{
    extern __shared__ uint32_t dsw[];
    // [0]: K buf0, [1]: K buf1, [2]: V buf0, [3]: V buf1

    const int tid  = threadIdx.x;
    const int lane = tid & 31;
    const int wid  = tid >> 5;
    const int g    = lane >> 2;
    const int tig  = lane & 3;
    const int q0   = blockIdx.x * 64;
    const int bh   = blockIdx.y;
    const int qr0  = q0 + wid * 16;

    const __half* qb  = g_q  + (size_t)bh * Ss * HDd;
    const __half* kb  = g_k  + (size_t)bh * Ss * HDd;
    const __half* vtb = g_vT + (size_t)bh * HDd * Ss;

    // Q fragments (q pre-scaled by 0.125 in GEMM epilogue)
    uint32_t qf[4][4];
    #pragma unroll
    for (int c = 0; c < 4; c++) {
        qf[c][0] = *(const uint32_t*)&qb[(size_t)(qr0 + g    ) * HDd + c * 16 + tig * 2    ];
        qf[c][1] = *(const uint32_t*)&qb[(size_t)(qr0 + g + 8) * HDd + c * 16 + tig * 2    ];
        qf[c][2] = *(const uint32_t*)&qb[(size_t)(qr0 + g    ) * HDd + c * 16 + tig * 2 + 8];
        qf[c][3] = *(const uint32_t*)&qb[(size_t)(qr0 + g + 8) * HDd + c * 16 + tig * 2 + 8];
    }

    float acc[8][4];
    #pragma unroll
    for (int na = 0; na < 8; na++)
        #pragma unroll
        for (int i = 0; i < 4; i++) acc[na][i] = 0.f;

    float m_lo = -INFINITY, m_hi = -INFINITY;
    float l_lo = 0.f, l_hi = 0.f;

    const int nt = q0 / 64 + 1;

    // loader: K rows = keys (64 x 128B), V rows = hd (64 x 128B of keys)
    auto issue_tile = [&](int kt, int buf) {
        uint32_t* Kd = dsw + buf * TSZ;
        uint32_t* Vd = dsw + (2 + buf) * TSZ;
        #pragma unroll
        for (int i = 0; i < 4; i++) {
            const int idx = tid + i * 128;      // 512 chunks each
            const int row = idx >> 3;
            const int c   = idx & 7;
            cp16(Kd + row * FP + c * 4, kb  + (size_t)(kt * 64 + row) * HDd + c * 8);
            cp16(Vd + row * FP + c * 4, vtb + (size_t)row * Ss + kt * 64 + c * 8);
        }
        CP_COMMIT();
    };

    issue_tile(0, 0);

    for (int kt = 0; kt < nt; kt++) {
        const int cur = kt & 1;
        CP_WAIT0();
        __syncthreads();
        if (kt + 1 < nt) issue_tile(kt + 1, cur ^ 1);

        const uint32_t* Kc = dsw + cur * TSZ;
        const uint32_t* Vc = dsw + (2 + cur) * TSZ;

        // ---- S = Q K^T ----
        float s[8][4];
        #pragma unroll
        for (int na = 0; na < 8; na++)
            #pragma unroll
            for (int i = 0; i < 4; i++) s[na][i] = 0.f;

        #pragma unroll
        for (int c = 0; c < 4; c++) {
            #pragma unroll
            for (int na = 0; na < 8; na++) {
                uint32_t b0 = Kc[(na * 8 + g) * FP + c * 8 + tig    ];
                uint32_t b1 = Kc[(na * 8 + g) * FP + c * 8 + tig + 4];
                mma_f16(s[na], qf[c][0], qf[c][1], qf[c][2], qf[c][3], b0, b1);
            }
        }

        // ---- causal mask (diagonal tile only) ----
        if (kt == nt - 1) {
            const int rlo = qr0 + g, rhi = qr0 + g + 8;
            #pragma unroll
            for (int na = 0; na < 8; na++) {
                const int c0 = kt * 64 + na * 8 + tig * 2;
                const int c1 = c0 + 1;
                if (c0 > rlo) s[na][0] = -INFINITY;
                if (c1 > rlo) s[na][1] = -INFINITY;
                if (c0 > rhi) s[na][2] = -INFINITY;
                if (c1 > rhi) s[na][3] = -INFINITY;
            }
        }

        // ---- online softmax ----
        float tm_lo = -INFINITY, tm_hi = -INFINITY;
        #pragma unroll
        for (int na = 0; na < 8; na++) {
            tm_lo = fmaxf(tm_lo, fmaxf(s[na][0], s[na][1]));
            tm_hi = fmaxf(tm_hi, fmaxf(s[na][2], s[na][3]));
        }
        tm_lo = fmaxf(tm_lo, __shfl_xor_sync(0xffffffffu, tm_lo, 1));
        tm_lo = fmaxf(tm_lo, __shfl_xor_sync(0xffffffffu, tm_lo, 2));
        tm_hi = fmaxf(tm_hi, __shfl_xor_sync(0xffffffffu, tm_hi, 1));
        tm_hi = fmaxf(tm_hi, __shfl_xor_sync(0xffffffffu, tm_hi, 2));

        const float mn_lo = fmaxf(m_lo, tm_lo);
        const float mn_hi = fmaxf(m_hi, tm_hi);
        const float sc_lo = __expf(m_lo - mn_lo);
        const float sc_hi = __expf(m_hi - mn_hi);

        float sum_lo = 0.f, sum_hi = 0.f;
        #pragma unroll
        for (int na = 0; na < 8; na++) {
            s[na][0] = __expf(s[na][0] - mn_lo);
            s[na][1] = __expf(s[na][1] - mn_lo);
            s[na][2] = __expf(s[na][2] - mn_hi);
            s[na][3] = __expf(s[na][3] - mn_hi);
            sum_lo += s[na][0] + s[na][1];
            sum_hi += s[na][2] + s[na][3];
        }
        sum_lo += __shfl_xor_sync(0xffffffffu, sum_lo, 1);
        sum_lo += __shfl_xor_sync(0xffffffffu, sum_lo, 2);
        sum_hi += __shfl_xor_sync(0xffffffffu, sum_hi, 1);
        sum_hi += __shfl_xor_sync(0xffffffffu, sum_hi, 2);

        l_lo = l_lo * sc_lo + sum_lo;  m_lo = mn_lo;
        l_hi = l_hi * sc_hi + sum_hi;  m_hi = mn_hi;

        #pragma unroll
        for (int na = 0; na < 8; na++) {
            acc[na][0] *= sc_lo; acc[na][1] *= sc_lo;
            acc[na][2] *= sc_hi; acc[na][3] *= sc_hi;
        }

        // ---- O += P V : P repacked register-to-register into A fragments ----
        #pragma unroll
        for (int c = 0; c < 4; c++) {
            const uint32_t a0 = pack_h2(s[2 * c    ][0], s[2 * c    ][1]);
            const uint32_t a1 = pack_h2(s[2 * c    ][2], s[2 * c    ][3]);
            const uint32_t a2 = pack_h2(s[2 * c + 1][0], s[2 * c + 1][1]);
            const uint32_t a3 = pack_h2(s[2 * c + 1][2], s[2 * c + 1][3]);
            #pragma unroll
            for (int na = 0; na < 8; na++) {
                uint32_t b0 = Vc[(na * 8 + g) * FP + c * 8 + tig    ];
                uint32_t b1 = Vc[(na * 8 + g) * FP + c * 8 + tig + 4];
                mma_f16(acc[na], a0, a1, a2, a3, b0, b1);
            }
        }
    }

    // ---- epilogue: normalize, pack fp16, write merged-head [B,S,D] ----
    const float inv_lo = 1.f / l_lo;
    const float inv_hi = 1.f / l_hi;
    const int b = bh / Hh, h = bh % Hh;
    __half* olo = g_o + ((size_t)b * Ss + (qr0 + g    )) * Dd + h * HDd;
    __half* ohi = g_o + ((size_t)b * Ss + (qr0 + g + 8)) * Dd + h * HDd;
    #pragma unroll
    for (int na = 0; na < 8; na++) {
        *(uint32_t*)&olo[na * 8 + tig * 2] = pack_h2(acc[na][0] * inv_lo, acc[na][1] * inv_lo);
        *(uint32_t*)&ohi[na * 8 + tig * 2] = pack_h2(acc[na][2] * inv_hi, acc[na][3] * inv_hi);
    }
}

// ---------------------------------------------------------------------------
extern "C" void kernel_launch(void* const* d_in, const int* in_sizes, int n_in,
                              void* d_out, int out_size)
{
    const float* x  = (const float*)d_in[0];
    const float* wq = (const float*)d_in[1];
    const float* bq = (const float*)d_in[2];
    const float* wk = (const float*)d_in[3];
    const float* bk = (const float*)d_in[4];
    const float* wv = (const float*)d_in[5];
    const float* bv = (const float*)d_in[6];
    const float* wo = (const float*)d_in[7];
    const float* bo = (const float*)d_in[8];
    float* out = (float*)d_out;

    cudaFuncSetAttribute(tc_gemm<true>,  cudaFuncAttributeMaxDynamicSharedMemorySize, GEMM_SMEM);
    cudaFuncSetAttribute(tc_gemm<false>, cudaFuncAttributeMaxDynamicSharedMemorySize, GEMM_SMEM);
    cudaFuncSetAttribute(flash_attn_tc,  cudaFuncAttributeMaxDynamicSharedMemorySize, FA_SMEM);

    // pre-pass: x -> fp16; weights -> transposed fp16
    round_x<<<Mm * Dd / (256 * 8), 256>>>(x);
    transpose_w<<<dim3(32, 32, 4), 256>>>(wq, wk, wv, wo);

    // fused QKV projection (fp16 tensor cores)
    dim3 qgrid(24, Mm / 128);             // (24, 64)
    tc_gemm<true><<<qgrid, 256, GEMM_SMEM>>>(bq, bk, bv, nullptr, nullptr);

    // attention
    dim3 agrid(Ss / 64, Bb * Hh);         // (32, 64)
    flash_attn_tc<<<agrid, 128, FA_SMEM>>>();

    // output projection
    dim3 ogrid(8, Mm / 128);              // (8, 64)
    tc_gemm<false><<<ogrid, 256, GEMM_SMEM>>>(nullptr, nullptr, nullptr, bo, out);
}

// round 13
// speedup vs baseline: 1.6862x; 1.0441x over previous
#include <cuda_runtime.h>
#include <cuda_fp16.h>
#include <math.h>
#include <stdint.h>

// Problem constants
#define Bb  4
#define Ss  2048
#define Dd  1024
#define Hh  16
#define HDd 64
#define Mm  (Bb*Ss)          // 8192

// Scratch (no allocation allowed -> __device__ globals). All fp16.
__device__ __align__(16) __half g_q [Bb*Hh*Ss*HDd];  // [B,H,S,HD], pre-scaled by 0.125*log2(e)
__device__ __align__(16) __half g_k [Bb*Hh*Ss*HDd];  // [B,H,S,HD]
__device__ __align__(16) __half g_vT[Bb*Hh*HDd*Ss];  // [B,H,HD,S]  (transposed!)
__device__ __align__(16) __half g_o [Bb*Ss*Dd];      // [B,S,D]
__device__ __align__(16) __half g_xt[Mm*Dd];         // x -> fp16 [M,K]
__device__ __align__(16) __half g_wt[4][Dd*Dd];      // weights TRANSPOSED [N,K], fp16

__device__ __forceinline__ uint32_t pack_h2(float lo, float hi) {
    __half2 h = __float22half2_rn(make_float2(lo, hi));
    return *(uint32_t*)&h;
}

__device__ __forceinline__ float ex2(float x) {
    float r;
    asm("ex2.approx.f32 %0, %1;" : "=f"(r) : "f"(x));
    return r;
}

__device__ __forceinline__ void mma_f16(float c[4],
                                        uint32_t a0, uint32_t a1, uint32_t a2, uint32_t a3,
                                        uint32_t b0, uint32_t b1) {
    asm volatile(
        "mma.sync.aligned.m16n8k16.row.col.f32.f16.f16.f32 "
        "{%0,%1,%2,%3}, {%4,%5,%6,%7}, {%8,%9}, {%0,%1,%2,%3};"
        : "+f"(c[0]), "+f"(c[1]), "+f"(c[2]), "+f"(c[3])
        : "r"(a0), "r"(a1), "r"(a2), "r"(a3), "r"(b0), "r"(b1));
}

__device__ __forceinline__ void ldsm_x4(uint32_t& r0, uint32_t& r1,
                                        uint32_t& r2, uint32_t& r3, uint32_t addr) {
    asm volatile("ldmatrix.sync.aligned.m8n8.x4.shared.b16 {%0,%1,%2,%3}, [%4];"
                 : "=r"(r0), "=r"(r1), "=r"(r2), "=r"(r3) : "r"(addr));
}

__device__ __forceinline__ void cp16(void* dst_smem, const void* src) {
    uint32_t d = (uint32_t)__cvta_generic_to_shared(dst_smem);
    asm volatile("cp.async.cg.shared.global [%0], [%1], 16;\n" :: "r"(d), "l"(src));
}
#define CP_COMMIT() asm volatile("cp.async.commit_group;\n" ::: "memory")
#define CP_WAIT1()  asm volatile("cp.async.wait_group 1;\n" ::: "memory")
#define CP_WAIT0()  asm volatile("cp.async.wait_group 0;\n" ::: "memory")

// ---------------------------------------------------------------------------
// Pre-pass 1: x (fp32) -> g_xt (fp16). 8 elems/thread.
// ---------------------------------------------------------------------------
__global__ __launch_bounds__(256)
void round_x(const float* __restrict__ x)
{
    const size_t i = ((size_t)blockIdx.x * 256 + threadIdx.x) * 8;
    float4 v0 = *(const float4*)(x + i);
    float4 v1 = *(const float4*)(x + i + 4);
    uint4 u;
    u.x = pack_h2(v0.x, v0.y);  u.y = pack_h2(v0.z, v0.w);
    u.z = pack_h2(v1.x, v1.y);  u.w = pack_h2(v1.z, v1.w);
    *(uint4*)(g_xt + i) = u;
}

// ---------------------------------------------------------------------------
// Pre-pass 2: transpose + convert weights: W[k][n] fp32 -> g_wt[w][n][k] fp16
// ---------------------------------------------------------------------------
__global__ __launch_bounds__(256)
void transpose_w(const float* __restrict__ wq, const float* __restrict__ wk,
                 const float* __restrict__ wv, const float* __restrict__ wo)
{
    __shared__ float sm[32][33];
    const int w = blockIdx.z;
    const float* src = (w == 0) ? wq : (w == 1) ? wk : (w == 2) ? wv : wo;
    __half* dst = g_wt[w];
    const int k0 = blockIdx.x * 32, n0 = blockIdx.y * 32;
    const int tx = threadIdx.x & 31, ty = threadIdx.x >> 5;
    #pragma unroll
    for (int i = 0; i < 4; i++)
        sm[ty + 8 * i][tx] = src[(size_t)(k0 + ty + 8 * i) * Dd + n0 + tx];
    __syncthreads();
    #pragma unroll
    for (int i = 0; i < 4; i++)
        dst[(size_t)(n0 + ty + 8 * i) * Dd + k0 + tx] = __float2half(sm[tx][ty + 8 * i]);
}

// ---------------------------------------------------------------------------
// fp16 tensor-core GEMM (m16n8k16), 3-stage cp.async ring, k-tile 32.
// [frozen from R12 except: Q epilogue scale now 0.125*log2(e) for exp2 flash]
// ---------------------------------------------------------------------------
#define PA 20
#define ROWW (PA)
#define ASTG (128*PA)
#define STGW (2*ASTG)
#define GEMM_SMEM (3*STGW*4)      // 61440 bytes

#define QSCALE 0.18033688011112042f   // 0.125 * log2(e)

template<bool QKV>
__global__ __launch_bounds__(256, 2)
void tc_gemm(const float* __restrict__ bq, const float* __restrict__ bk,
             const float* __restrict__ bv, const float* __restrict__ bo,
             float* __restrict__ out_param)
{
    extern __shared__ uint32_t dsw[];

    int sel; const __half* A; const __half* W; const float* bias;
    int bnx;
    if (QKV) {
        sel = blockIdx.x >> 3;  bnx = blockIdx.x & 7;
        A = g_xt;  W = g_wt[sel];
        bias = (sel == 0) ? bq : (sel == 1) ? bk : bv;
    } else {
        sel = 3; bnx = blockIdx.x;
        A = g_o;  W = g_wt[3];  bias = bo;
    }

    const int t    = threadIdx.x;
    const int lane = t & 31;
    const int wid  = t >> 5;
    const int wm   = (wid & 3) * 32;
    const int wn   = (wid >> 2) * 64;
    const int g    = lane >> 2;
    const int tig  = lane & 3;

    const int bm = blockIdx.y * 128;
    const int bn = bnx * 128;

    const int lr = t >> 1;
    const int lcp = t & 1;
    const __half* Arow = A + (size_t)(bm + lr) * Dd + lcp * 16;
    const __half* Wrow = W + (size_t)(bn + lr) * Dd + lcp * 16;

    const int NT = Dd / 32;

    auto issue = [&](int kt, int stg) {
        if (kt < NT) {
            const int k0 = kt * 32;
            uint32_t* Aw = dsw + stg * STGW;
            uint32_t* Bw = Aw + ASTG;
            cp16(Aw + lr * ROWW + lcp * 8,     Arow + k0);
            cp16(Aw + lr * ROWW + lcp * 8 + 4, Arow + k0 + 8);
            cp16(Bw + lr * ROWW + lcp * 8,     Wrow + k0);
            cp16(Bw + lr * ROWW + lcp * 8 + 4, Wrow + k0 + 8);
        }
        CP_COMMIT();
    };

    float acc[2][8][4];
    #pragma unroll
    for (int ma = 0; ma < 2; ma++)
        #pragma unroll
        for (int na = 0; na < 8; na++)
            #pragma unroll
            for (int i = 0; i < 4; i++) acc[ma][na][i] = 0.f;

    issue(0, 0);
    issue(1, 1);

    for (int kt = 0; kt < NT; kt++) {
        const int cur = kt % 3;
        CP_WAIT1();
        __syncthreads();
        issue(kt + 2, (kt + 2) % 3);

        const uint32_t* Aw = dsw + cur * STGW;
        const uint32_t* Bw = Aw + ASTG;

        #pragma unroll
        for (int ks = 0; ks < 2; ks++) {
            const int kw = ks * 8;
            uint32_t a[2][4];
            #pragma unroll
            for (int ma = 0; ma < 2; ma++) {
                const int r0 = wm + ma * 16 + g;
                a[ma][0] = Aw[(r0    ) * ROWW + kw + tig    ];
                a[ma][1] = Aw[(r0 + 8) * ROWW + kw + tig    ];
                a[ma][2] = Aw[(r0    ) * ROWW + kw + tig + 4];
                a[ma][3] = Aw[(r0 + 8) * ROWW + kw + tig + 4];
            }
            #pragma unroll
            for (int na = 0; na < 8; na++) {
                const int n0 = wn + na * 8 + g;
                uint32_t b0 = Bw[n0 * ROWW + kw + tig    ];
                uint32_t b1 = Bw[n0 * ROWW + kw + tig + 4];
                #pragma unroll
                for (int ma = 0; ma < 2; ma++)
                    mma_f16(acc[ma][na], a[ma][0], a[ma][1], a[ma][2], a[ma][3], b0, b1);
            }
        }
    }

    #pragma unroll
    for (int ma = 0; ma < 2; ma++) {
        #pragma unroll
        for (int na = 0; na < 8; na++) {
            const int row0 = bm + wm + ma * 16 + g;
            const int col  = bn + wn + na * 8 + tig * 2;
            const float bia0 = bias[col], bia1 = bias[col + 1];
            #pragma unroll
            for (int half_i = 0; half_i < 2; half_i++) {
                const int mrow = row0 + half_i * 8;
                float v0 = acc[ma][na][half_i * 2 + 0] + bia0;
                float v1 = acc[ma][na][half_i * 2 + 1] + bia1;
                if (QKV) {
                    const int b = mrow / Ss, s = mrow % Ss;
                    const int h = col / HDd, d = col % HDd;
                    if (sel == 0) { v0 *= QSCALE; v1 *= QSCALE; }
                    if (sel == 2) {
                        __half* dst = g_vT + (((size_t)b * Hh + h) * HDd) * Ss + s;
                        dst[(size_t)d * Ss]       = __float2half(v0);
                        dst[(size_t)(d + 1) * Ss] = __float2half(v1);
                    } else {
                        __half* dst = (sel == 0) ? g_q : g_k;
                        *(uint32_t*)&dst[(((size_t)b * Hh + h) * Ss + s) * HDd + d] =
                            pack_h2(v0, v1);
                    }
                } else {
                    *(float2*)&out_param[(size_t)mrow * Dd + col] = make_float2(v0, v1);
                }
            }
        }
    }
}

// ---------------------------------------------------------------------------
// fp16 tensor-core flash attention (causal), m16n8k16, FA2-style.
// R13: ldmatrix.x4 for all K/V fragment loads; exp2 domain (scale folded
// into Q); per-thread partial softmax denominator (end-of-loop reduce).
// ---------------------------------------------------------------------------
#define FP 36                         // words per smem row
#define TSZ (64*FP)                   // words per tile (2304)
#define FA_SMEM (4*TSZ*4)             // K x2 + V x2 = 36864 bytes

__global__ __launch_bounds__(128)
void flash_attn_tc()
{
    extern __shared__ uint32_t dsw[];
    // [0]: K buf0, [1]: K buf1, [2]: V buf0, [3]: V buf1

    const int tid  = threadIdx.x;
    const int lane = tid & 31;
    const int wid  = tid >> 5;
    const int g    = lane >> 2;
    const int tig  = lane & 3;
    const int q0   = blockIdx.x * 64;
    const int bh   = blockIdx.y;
    const int qr0  = q0 + wid * 16;

    const __half* qb  = g_q  + (size_t)bh * Ss * HDd;
    const __half* kb  = g_k  + (size_t)bh * Ss * HDd;
    const __half* vtb = g_vT + (size_t)bh * HDd * Ss;

    const uint32_t sm0 = (uint32_t)__cvta_generic_to_shared(dsw);

    // per-lane ldmatrix offset (bytes): matrix = (na-parity, k-half), row = lane%8
    const int lrow = lane & 7;
    const int lmat = lane >> 3;
    const uint32_t lofs = (uint32_t)((((lmat >> 1) * 8 + lrow) * FP + (lmat & 1) * 4) * 4);

    // Q fragments (pre-scaled by 0.125*log2e in GEMM epilogue)
    uint32_t qf[4][4];
    #pragma unroll
    for (int c = 0; c < 4; c++) {
        qf[c][0] = *(const uint32_t*)&qb[(size_t)(qr0 + g    ) * HDd + c * 16 + tig * 2    ];
        qf[c][1] = *(const uint32_t*)&qb[(size_t)(qr0 + g + 8) * HDd + c * 16 + tig * 2    ];
        qf[c][2] = *(const uint32_t*)&qb[(size_t)(qr0 + g    ) * HDd + c * 16 + tig * 2 + 8];
        qf[c][3] = *(const uint32_t*)&qb[(size_t)(qr0 + g + 8) * HDd + c * 16 + tig * 2 + 8];
    }

    float acc[8][4];
    #pragma unroll
    for (int na = 0; na < 8; na++)
        #pragma unroll
        for (int i = 0; i < 4; i++) acc[na][i] = 0.f;

    float m_lo = -INFINITY, m_hi = -INFINITY;
    float l_lo = 0.f, l_hi = 0.f;        // per-thread partials (reduced at end)

    const int nt = q0 / 64 + 1;

    auto issue_tile = [&](int kt, int buf) {
        uint32_t* Kd = dsw + buf * TSZ;
        uint32_t* Vd = dsw + (2 + buf) * TSZ;
        #pragma unroll
        for (int i = 0; i < 4; i++) {
            const int idx = tid + i * 128;
            const int row = idx >> 3;
            const int c   = idx & 7;
            cp16(Kd + row * FP + c * 4, kb  + (size_t)(kt * 64 + row) * HDd + c * 8);
            cp16(Vd + row * FP + c * 4, vtb + (size_t)row * Ss + kt * 64 + c * 8);
        }
        CP_COMMIT();
    };

    issue_tile(0, 0);

    for (int kt = 0; kt < nt; kt++) {
        const int cur = kt & 1;
        CP_WAIT0();
        __syncthreads();
        if (kt + 1 < nt) issue_tile(kt + 1, cur ^ 1);

        const uint32_t Kc = sm0 + (uint32_t)(cur * TSZ) * 4 + lofs;
        const uint32_t Vc = sm0 + (uint32_t)((2 + cur) * TSZ) * 4 + lofs;

        // ---- S = Q K^T (log2 domain; scale folded into Q) ----
        float s[8][4];
        #pragma unroll
        for (int na = 0; na < 8; na++)
            #pragma unroll
            for (int i = 0; i < 4; i++) s[na][i] = 0.f;

        #pragma unroll
        for (int c = 0; c < 4; c++) {
            #pragma unroll
            for (int p = 0; p < 4; p++) {
                uint32_t b00, b01, b10, b11;
                ldsm_x4(b00, b01, b10, b11, Kc + (uint32_t)((p * 16 * FP + c * 8) * 4));
                mma_f16(s[2*p    ], qf[c][0], qf[c][1], qf[c][2], qf[c][3], b00, b01);
                mma_f16(s[2*p + 1], qf[c][0], qf[c][1], qf[c][2], qf[c][3], b10, b11);
            }
        }

        // ---- causal mask (diagonal tile only) ----
        if (kt == nt - 1) {
            const int rlo = qr0 + g, rhi = qr0 + g + 8;
            #pragma unroll
            for (int na = 0; na < 8; na++) {
                const int c0 = kt * 64 + na * 8 + tig * 2;
                const int c1 = c0 + 1;
                if (c0 > rlo) s[na][0] = -INFINITY;
                if (c1 > rlo) s[na][1] = -INFINITY;
                if (c0 > rhi) s[na][2] = -INFINITY;
                if (c1 > rhi) s[na][3] = -INFINITY;
            }
        }

        // ---- online softmax (exp2 domain) ----
        float tm_lo = -INFINITY, tm_hi = -INFINITY;
        #pragma unroll
        for (int na = 0; na < 8; na++) {
            tm_lo = fmaxf(tm_lo, fmaxf(s[na][0], s[na][1]));
            tm_hi = fmaxf(tm_hi, fmaxf(s[na][2], s[na][3]));
        }
        tm_lo = fmaxf(tm_lo, __shfl_xor_sync(0xffffffffu, tm_lo, 1));
        tm_lo = fmaxf(tm_lo, __shfl_xor_sync(0xffffffffu, tm_lo, 2));
        tm_hi = fmaxf(tm_hi, __shfl_xor_sync(0xffffffffu, tm_hi, 1));
        tm_hi = fmaxf(tm_hi, __shfl_xor_sync(0xffffffffu, tm_hi, 2));

        const float mn_lo = fmaxf(m_lo, tm_lo);
        const float mn_hi = fmaxf(m_hi, tm_hi);
        const float sc_lo = ex2(m_lo - mn_lo);
        const float sc_hi = ex2(m_hi - mn_hi);
        m_lo = mn_lo;  m_hi = mn_hi;

        float sum_lo = 0.f, sum_hi = 0.f;
        #pragma unroll
        for (int na = 0; na < 8; na++) {
            s[na][0] = ex2(s[na][0] - mn_lo);
            s[na][1] = ex2(s[na][1] - mn_lo);
            s[na][2] = ex2(s[na][2] - mn_hi);
            s[na][3] = ex2(s[na][3] - mn_hi);
            sum_lo += s[na][0] + s[na][1];
            sum_hi += s[na][2] + s[na][3];
        }
        l_lo = l_lo * sc_lo + sum_lo;    // per-thread partial
        l_hi = l_hi * sc_hi + sum_hi;

        #pragma unroll
        for (int na = 0; na < 8; na++) {
            acc[na][0] *= sc_lo; acc[na][1] *= sc_lo;
            acc[na][2] *= sc_hi; acc[na][3] *= sc_hi;
        }

        // ---- O += P V : P repacked register-to-register into A fragments ----
        #pragma unroll
        for (int c = 0; c < 4; c++) {
            const uint32_t a0 = pack_h2(s[2 * c    ][0], s[2 * c    ][1]);
            const uint32_t a1 = pack_h2(s[2 * c    ][2], s[2 * c    ][3]);
            const uint32_t a2 = pack_h2(s[2 * c + 1][0], s[2 * c + 1][1]);
            const uint32_t a3 = pack_h2(s[2 * c + 1][2], s[2 * c + 1][3]);
            #pragma unroll
            for (int p = 0; p < 4; p++) {
                uint32_t b00, b01, b10, b11;
                ldsm_x4(b00, b01, b10, b11, Vc + (uint32_t)((p * 16 * FP + c * 8) * 4));
                mma_f16(acc[2*p    ], a0, a1, a2, a3, b00, b01);
                mma_f16(acc[2*p + 1], a0, a1, a2, a3, b10, b11);
            }
        }
    }

    // ---- final softmax-denominator reduce (quad) ----
    l_lo += __shfl_xor_sync(0xffffffffu, l_lo, 1);
    l_lo += __shfl_xor_sync(0xffffffffu, l_lo, 2);
    l_hi += __shfl_xor_sync(0xffffffffu, l_hi, 1);
    l_hi += __shfl_xor_sync(0xffffffffu, l_hi, 2);

    // ---- epilogue: normalize, pack fp16, write merged-head [B,S,D] ----
    const float inv_lo = 1.f / l_lo;
    const float inv_hi = 1.f / l_hi;
    const int b = bh / Hh, h = bh % Hh;
    __half* olo = g_o + ((size_t)b * Ss + (qr0 + g    )) * Dd + h * HDd;
    __half* ohi = g_o + ((size_t)b * Ss + (qr0 + g + 8)) * Dd + h * HDd;
    #pragma unroll
    for (int na = 0; na < 8; na++) {
        *(uint32_t*)&olo[na * 8 + tig * 2] = pack_h2(acc[na][0] * inv_lo, acc[na][1] * inv_lo);
        *(uint32_t*)&ohi[na * 8 + tig * 2] = pack_h2(acc[na][2] * inv_hi, acc[na][3] * inv_hi);
    }
}

// ---------------------------------------------------------------------------
extern "C" void kernel_launch(void* const* d_in, const int* in_sizes, int n_in,
                              void* d_out, int out_size)
{
    const float* x  = (const float*)d_in[0];
    const float* wq = (const float*)d_in[1];
    const float* bq = (const float*)d_in[2];
    const float* wk = (const float*)d_in[3];
    const float* bk = (const float*)d_in[4];
    const float* wv = (const float*)d_in[5];
    const float* bv = (const float*)d_in[6];
    const float* wo = (const float*)d_in[7];
    const float* bo = (const float*)d_in[8];
    float* out = (float*)d_out;

    cudaFuncSetAttribute(tc_gemm<true>,  cudaFuncAttributeMaxDynamicSharedMemorySize, GEMM_SMEM);
    cudaFuncSetAttribute(tc_gemm<false>, cudaFuncAttributeMaxDynamicSharedMemorySize, GEMM_SMEM);
    cudaFuncSetAttribute(flash_attn_tc,  cudaFuncAttributeMaxDynamicSharedMemorySize, FA_SMEM);

    // pre-pass: x -> fp16; weights -> transposed fp16
    round_x<<<Mm * Dd / (256 * 8), 256>>>(x);
    transpose_w<<<dim3(32, 32, 4), 256>>>(wq, wk, wv, wo);

    // fused QKV projection (fp16 tensor cores)
    dim3 qgrid(24, Mm / 128);             // (24, 64)
    tc_gemm<true><<<qgrid, 256, GEMM_SMEM>>>(bq, bk, bv, nullptr, nullptr);

    // attention
    dim3 agrid(Ss / 64, Bb * Hh);         // (32, 64)
    flash_attn_tc<<<agrid, 128, FA_SMEM>>>();

    // output projection
    dim3 ogrid(8, Mm / 128);              // (8, 64)
    tc_gemm<false><<<ogrid, 256, GEMM_SMEM>>>(nullptr, nullptr, nullptr, bo, out);
}

// round 14
// speedup vs baseline: 1.7125x; 1.0156x over previous
#include <cuda_runtime.h>
#include <cuda_fp16.h>
#include <math.h>
#include <stdint.h>

// Problem constants
#define Bb  4
#define Ss  2048
#define Dd  1024
#define Hh  16
#define HDd 64
#define Mm  (Bb*Ss)          // 8192

// Scratch (no allocation allowed -> __device__ globals). All fp16.
__device__ __align__(16) __half g_q [Bb*Hh*Ss*HDd];  // [B,H,S,HD], pre-scaled by 0.125*log2(e)
__device__ __align__(16) __half g_k [Bb*Hh*Ss*HDd];  // [B,H,S,HD]
__device__ __align__(16) __half g_vT[Bb*Hh*HDd*Ss];  // [B,H,HD,S]  (transposed!)
__device__ __align__(16) __half g_o [Bb*Ss*Dd];      // [B,S,D]
__device__ __align__(16) __half g_xt[Mm*Dd];         // x -> fp16 [M,K]
__device__ __align__(16) __half g_wt[4][Dd*Dd];      // weights TRANSPOSED [N,K], fp16

__device__ __forceinline__ uint32_t pack_h2(float lo, float hi) {
    __half2 h = __float22half2_rn(make_float2(lo, hi));
    return *(uint32_t*)&h;
}

__device__ __forceinline__ float ex2(float x) {
    float r;
    asm("ex2.approx.f32 %0, %1;" : "=f"(r) : "f"(x));
    return r;
}

__device__ __forceinline__ void mma_f16(float c[4],
                                        uint32_t a0, uint32_t a1, uint32_t a2, uint32_t a3,
                                        uint32_t b0, uint32_t b1) {
    asm volatile(
        "mma.sync.aligned.m16n8k16.row.col.f32.f16.f16.f32 "
        "{%0,%1,%2,%3}, {%4,%5,%6,%7}, {%8,%9}, {%0,%1,%2,%3};"
        : "+f"(c[0]), "+f"(c[1]), "+f"(c[2]), "+f"(c[3])
        : "r"(a0), "r"(a1), "r"(a2), "r"(a3), "r"(b0), "r"(b1));
}

__device__ __forceinline__ void ldsm_x4(uint32_t& r0, uint32_t& r1,
                                        uint32_t& r2, uint32_t& r3, uint32_t addr) {
    asm volatile("ldmatrix.sync.aligned.m8n8.x4.shared.b16 {%0,%1,%2,%3}, [%4];"
                 : "=r"(r0), "=r"(r1), "=r"(r2), "=r"(r3) : "r"(addr));
}

__device__ __forceinline__ void cp16(void* dst_smem, const void* src) {
    uint32_t d = (uint32_t)__cvta_generic_to_shared(dst_smem);
    asm volatile("cp.async.cg.shared.global [%0], [%1], 16;\n" :: "r"(d), "l"(src));
}
#define CP_COMMIT() asm volatile("cp.async.commit_group;\n" ::: "memory")
#define CP_WAIT1()  asm volatile("cp.async.wait_group 1;\n" ::: "memory")
#define CP_WAIT0()  asm volatile("cp.async.wait_group 0;\n" ::: "memory")

// ---------------------------------------------------------------------------
// Pre-pass 1: x (fp32) -> g_xt (fp16). 8 elems/thread.
// ---------------------------------------------------------------------------
__global__ __launch_bounds__(256)
void round_x(const float* __restrict__ x)
{
    const size_t i = ((size_t)blockIdx.x * 256 + threadIdx.x) * 8;
    float4 v0 = *(const float4*)(x + i);
    float4 v1 = *(const float4*)(x + i + 4);
    uint4 u;
    u.x = pack_h2(v0.x, v0.y);  u.y = pack_h2(v0.z, v0.w);
    u.z = pack_h2(v1.x, v1.y);  u.w = pack_h2(v1.z, v1.w);
    *(uint4*)(g_xt + i) = u;
}

// ---------------------------------------------------------------------------
// Pre-pass 2: transpose + convert weights: W[k][n] fp32 -> g_wt[w][n][k] fp16
// ---------------------------------------------------------------------------
__global__ __launch_bounds__(256)
void transpose_w(const float* __restrict__ wq, const float* __restrict__ wk,
                 const float* __restrict__ wv, const float* __restrict__ wo)
{
    __shared__ float sm[32][33];
    const int w = blockIdx.z;
    const float* src = (w == 0) ? wq : (w == 1) ? wk : (w == 2) ? wv : wo;
    __half* dst = g_wt[w];
    const int k0 = blockIdx.x * 32, n0 = blockIdx.y * 32;
    const int tx = threadIdx.x & 31, ty = threadIdx.x >> 5;
    #pragma unroll
    for (int i = 0; i < 4; i++)
        sm[ty + 8 * i][tx] = src[(size_t)(k0 + ty + 8 * i) * Dd + n0 + tx];
    __syncthreads();
    #pragma unroll
    for (int i = 0; i < 4; i++)
        dst[(size_t)(n0 + ty + 8 * i) * Dd + k0 + tx] = __float2half(sm[tx][ty + 8 * i]);
}

// ---------------------------------------------------------------------------
// fp16 tensor-core GEMM (m16n8k16), 3-stage cp.async ring, k-tile 64.
// R14: ldmatrix.x4 fragment loads, 16 mainloop iterations (vs 32),
// pitch GP=36 words (64 halves data + pad) -> conflict-free ldmatrix phases.
// Same math order as R13 -> bit-identical output.
// ---------------------------------------------------------------------------
#define GP 36                      // words per smem row (k64 = 32 words + 4 pad)
#define GASTG (128*GP)             // words per A (or B) stage: 4608
#define GSTGW (2*GASTG)            // words per stage A+B: 9216 (36864 B)
#define GEMM_SMEM (3*GSTGW*4)      // 110592 bytes

#define QSCALE 0.18033688011112042f   // 0.125 * log2(e)

template<bool QKV>
__global__ __launch_bounds__(256, 2)
void tc_gemm(const float* __restrict__ bq, const float* __restrict__ bk,
             const float* __restrict__ bv, const float* __restrict__ bo,
             float* __restrict__ out_param)
{
    extern __shared__ uint32_t dsw[];

    int sel; const __half* A; const __half* W; const float* bias;
    int bnx;
    if (QKV) {
        sel = blockIdx.x >> 3;  bnx = blockIdx.x & 7;
        A = g_xt;  W = g_wt[sel];
        bias = (sel == 0) ? bq : (sel == 1) ? bk : bv;
    } else {
        sel = 3; bnx = blockIdx.x;
        A = g_o;  W = g_wt[3];  bias = bo;
    }

    const int t    = threadIdx.x;
    const int lane = t & 31;
    const int wid  = t >> 5;
    const int wm   = (wid & 3) * 32;
    const int wn   = (wid >> 2) * 64;
    const int g    = lane >> 2;
    const int tig  = lane & 3;

    const int bm = blockIdx.y * 128;
    const int bn = bnx * 128;

    const uint32_t sm0 = (uint32_t)__cvta_generic_to_shared(dsw);

    // per-lane ldmatrix byte offsets (added to tile-base + row-block + k-word)
    const int lrow = lane & 7;
    const int lmat = lane >> 3;
    // A: matrices = (m-half, k-half): r0=(m0..7,k0) r1=(m8..15,k0) r2=(m0..7,k8) r3=(m8..15,k8)
    const uint32_t lofsA = (uint32_t)((((lmat & 1) * 8 + lrow) * GP + (lmat >> 1) * 4) * 4);
    // B: matrices = (n-half, k-half): r0=(n0..7,k0) r1=(n0..7,k8) r2=(n8..15,k0) r3=(n8..15,k8)
    const uint32_t lofsB = (uint32_t)((((lmat >> 1) * 8 + lrow) * GP + (lmat & 1) * 4) * 4);

    // loader: thread -> row lr (0..127), half-row lcp; 4 chunks A + 4 chunks B
    const int lr = t >> 1;
    const int lcp = t & 1;
    const __half* Arow = A + (size_t)(bm + lr) * Dd + lcp * 32;
    const __half* Wrow = W + (size_t)(bn + lr) * Dd + lcp * 32;

    const int NT = Dd / 64;   // 16 k-tiles

    auto issue = [&](int kt, int stg) {
        if (kt < NT) {
            const int k0 = kt * 64;
            uint32_t* Aw = dsw + stg * GSTGW;
            uint32_t* Bw = Aw + GASTG;
            #pragma unroll
            for (int j = 0; j < 4; j++) {
                cp16(Aw + lr * GP + (lcp * 4 + j) * 4, Arow + k0 + j * 8);
                cp16(Bw + lr * GP + (lcp * 4 + j) * 4, Wrow + k0 + j * 8);
            }
        }
        CP_COMMIT();
    };

    float acc[2][8][4];
    #pragma unroll
    for (int ma = 0; ma < 2; ma++)
        #pragma unroll
        for (int na = 0; na < 8; na++)
            #pragma unroll
            for (int i = 0; i < 4; i++) acc[ma][na][i] = 0.f;

    issue(0, 0);
    issue(1, 1);

    for (int kt = 0; kt < NT; kt++) {
        const int cur = kt % 3;
        CP_WAIT1();
        __syncthreads();
        issue(kt + 2, (kt + 2) % 3);

        const uint32_t Abase = sm0 + (uint32_t)(cur * GSTGW) * 4;
        const uint32_t Bbase = Abase + (uint32_t)GASTG * 4;

        #pragma unroll
        for (int ks = 0; ks < 4; ks++) {            // four k16 chunks
            const uint32_t kwo = (uint32_t)(ks * 8 * 4);   // k-word offset (bytes)
            uint32_t a[2][4];
            #pragma unroll
            for (int ma = 0; ma < 2; ma++) {
                const uint32_t ra = Abase + (uint32_t)((wm + ma * 16) * GP) * 4 + kwo + lofsA;
                ldsm_x4(a[ma][0], a[ma][1], a[ma][2], a[ma][3], ra);
            }
            #pragma unroll
            for (int p = 0; p < 4; p++) {
                uint32_t b00, b01, b10, b11;
                const uint32_t rb = Bbase + (uint32_t)((wn + p * 16) * GP) * 4 + kwo + lofsB;
                ldsm_x4(b00, b01, b10, b11, rb);
                #pragma unroll
                for (int ma = 0; ma < 2; ma++) {
                    mma_f16(acc[ma][2*p    ], a[ma][0], a[ma][1], a[ma][2], a[ma][3], b00, b01);
                    mma_f16(acc[ma][2*p + 1], a[ma][0], a[ma][1], a[ma][2], a[ma][3], b10, b11);
                }
            }
        }
    }

    // ---- epilogue (unchanged) ----
    #pragma unroll
    for (int ma = 0; ma < 2; ma++) {
        #pragma unroll
        for (int na = 0; na < 8; na++) {
            const int row0 = bm + wm + ma * 16 + g;
            const int col  = bn + wn + na * 8 + tig * 2;
            const float bia0 = bias[col], bia1 = bias[col + 1];
            #pragma unroll
            for (int half_i = 0; half_i < 2; half_i++) {
                const int mrow = row0 + half_i * 8;
                float v0 = acc[ma][na][half_i * 2 + 0] + bia0;
                float v1 = acc[ma][na][half_i * 2 + 1] + bia1;
                if (QKV) {
                    const int b = mrow / Ss, s = mrow % Ss;
                    const int h = col / HDd, d = col % HDd;
                    if (sel == 0) { v0 *= QSCALE; v1 *= QSCALE; }
                    if (sel == 2) {
                        __half* dst = g_vT + (((size_t)b * Hh + h) * HDd) * Ss + s;
                        dst[(size_t)d * Ss]       = __float2half(v0);
                        dst[(size_t)(d + 1) * Ss] = __float2half(v1);
                    } else {
                        __half* dst = (sel == 0) ? g_q : g_k;
                        *(uint32_t*)&dst[(((size_t)b * Hh + h) * Ss + s) * HDd + d] =
                            pack_h2(v0, v1);
                    }
                } else {
                    *(float2*)&out_param[(size_t)mrow * Dd + col] = make_float2(v0, v1);
                }
            }
        }
    }
}

// ---------------------------------------------------------------------------
// fp16 tensor-core flash attention (causal), m16n8k16, FA2-style.
// [frozen from R13]
// ---------------------------------------------------------------------------
#define FP 36                         // words per smem row
#define TSZ (64*FP)                   // words per tile (2304)
#define FA_SMEM (4*TSZ*4)             // K x2 + V x2 = 36864 bytes

__global__ __launch_bounds__(128)
void flash_attn_tc()
{
    extern __shared__ uint32_t dsw[];

    const int tid  = threadIdx.x;
    const int lane = tid & 31;
    const int wid  = tid >> 5;
    const int g    = lane >> 2;
    const int tig  = lane & 3;
    const int q0   = blockIdx.x * 64;
    const int bh   = blockIdx.y;
    const int qr0  = q0 + wid * 16;

    const __half* qb  = g_q  + (size_t)bh * Ss * HDd;
    const __half* kb  = g_k  + (size_t)bh * Ss * HDd;
    const __half* vtb = g_vT + (size_t)bh * HDd * Ss;

    const uint32_t sm0 = (uint32_t)__cvta_generic_to_shared(dsw);

    const int lrow = lane & 7;
    const int lmat = lane >> 3;
    const uint32_t lofs = (uint32_t)((((lmat >> 1) * 8 + lrow) * FP + (lmat & 1) * 4) * 4);

    uint32_t qf[4][4];
    #pragma unroll
    for (int c = 0; c < 4; c++) {
        qf[c][0] = *(const uint32_t*)&qb[(size_t)(qr0 + g    ) * HDd + c * 16 + tig * 2    ];
        qf[c][1] = *(const uint32_t*)&qb[(size_t)(qr0 + g + 8) * HDd + c * 16 + tig * 2    ];
        qf[c][2] = *(const uint32_t*)&qb[(size_t)(qr0 + g    ) * HDd + c * 16 + tig * 2 + 8];
        qf[c][3] = *(const uint32_t*)&qb[(size_t)(qr0 + g + 8) * HDd + c * 16 + tig * 2 + 8];
    }

    float acc[8][4];
    #pragma unroll
    for (int na = 0; na < 8; na++)
        #pragma unroll
        for (int i = 0; i < 4; i++) acc[na][i] = 0.f;

    float m_lo = -INFINITY, m_hi = -INFINITY;
    float l_lo = 0.f, l_hi = 0.f;

    const int nt = q0 / 64 + 1;

    auto issue_tile = [&](int kt, int buf) {
        uint32_t* Kd = dsw + buf * TSZ;
        uint32_t* Vd = dsw + (2 + buf) * TSZ;
        #pragma unroll
        for (int i = 0; i < 4; i++) {
            const int idx = tid + i * 128;
            const int row = idx >> 3;
            const int c   = idx & 7;
            cp16(Kd + row * FP + c * 4, kb  + (size_t)(kt * 64 + row) * HDd + c * 8);
            cp16(Vd + row * FP + c * 4, vtb + (size_t)row * Ss + kt * 64 + c * 8);
        }
        CP_COMMIT();
    };

    issue_tile(0, 0);

    for (int kt = 0; kt < nt; kt++) {
        const int cur = kt & 1;
        CP_WAIT0();
        __syncthreads();
        if (kt + 1 < nt) issue_tile(kt + 1, cur ^ 1);

        const uint32_t Kc = sm0 + (uint32_t)(cur * TSZ) * 4 + lofs;
        const uint32_t Vc = sm0 + (uint32_t)((2 + cur) * TSZ) * 4 + lofs;

        float s[8][4];
        #pragma unroll
        for (int na = 0; na < 8; na++)
            #pragma unroll
            for (int i = 0; i < 4; i++) s[na][i] = 0.f;

        #pragma unroll
        for (int c = 0; c < 4; c++) {
            #pragma unroll
            for (int p = 0; p < 4; p++) {
                uint32_t b00, b01, b10, b11;
                ldsm_x4(b00, b01, b10, b11, Kc + (uint32_t)((p * 16 * FP + c * 8) * 4));
                mma_f16(s[2*p    ], qf[c][0], qf[c][1], qf[c][2], qf[c][3], b00, b01);
                mma_f16(s[2*p + 1], qf[c][0], qf[c][1], qf[c][2], qf[c][3], b10, b11);
            }
        }

        if (kt == nt - 1) {
            const int rlo = qr0 + g, rhi = qr0 + g + 8;
            #pragma unroll
            for (int na = 0; na < 8; na++) {
                const int c0 = kt * 64 + na * 8 + tig * 2;
                const int c1 = c0 + 1;
                if (c0 > rlo) s[na][0] = -INFINITY;
                if (c1 > rlo) s[na][1] = -INFINITY;
                if (c0 > rhi) s[na][2] = -INFINITY;
                if (c1 > rhi) s[na][3] = -INFINITY;
            }
        }

        float tm_lo = -INFINITY, tm_hi = -INFINITY;
        #pragma unroll
        for (int na = 0; na < 8; na++) {
            tm_lo = fmaxf(tm_lo, fmaxf(s[na][0], s[na][1]));
            tm_hi = fmaxf(tm_hi, fmaxf(s[na][2], s[na][3]));
        }
        tm_lo = fmaxf(tm_lo, __shfl_xor_sync(0xffffffffu, tm_lo, 1));
        tm_lo = fmaxf(tm_lo, __shfl_xor_sync(0xffffffffu, tm_lo, 2));
        tm_hi = fmaxf(tm_hi, __shfl_xor_sync(0xffffffffu, tm_hi, 1));
        tm_hi = fmaxf(tm_hi, __shfl_xor_sync(0xffffffffu, tm_hi, 2));

        const float mn_lo = fmaxf(m_lo, tm_lo);
        const float mn_hi = fmaxf(m_hi, tm_hi);
        const float sc_lo = ex2(m_lo - mn_lo);
        const float sc_hi = ex2(m_hi - mn_hi);
        m_lo = mn_lo;  m_hi = mn_hi;

        float sum_lo = 0.f, sum_hi = 0.f;
        #pragma unroll
        for (int na = 0; na < 8; na++) {
            s[na][0] = ex2(s[na][0] - mn_lo);
            s[na][1] = ex2(s[na][1] - mn_lo);
            s[na][2] = ex2(s[na][2] - mn_hi);
            s[na][3] = ex2(s[na][3] - mn_hi);
            sum_lo += s[na][0] + s[na][1];
            sum_hi += s[na][2] + s[na][3];
        }
        l_lo = l_lo * sc_lo + sum_lo;
        l_hi = l_hi * sc_hi + sum_hi;

        #pragma unroll
        for (int na = 0; na < 8; na++) {
            acc[na][0] *= sc_lo; acc[na][1] *= sc_lo;
            acc[na][2] *= sc_hi; acc[na][3] *= sc_hi;
        }

        #pragma unroll
        for (int c = 0; c < 4; c++) {
            const uint32_t a0 = pack_h2(s[2 * c    ][0], s[2 * c    ][1]);
            const uint32_t a1 = pack_h2(s[2 * c    ][2], s[2 * c    ][3]);
            const uint32_t a2 = pack_h2(s[2 * c + 1][0], s[2 * c + 1][1]);
            const uint32_t a3 = pack_h2(s[2 * c + 1][2], s[2 * c + 1][3]);
            #pragma unroll
            for (int p = 0; p < 4; p++) {
                uint32_t b00, b01, b10, b11;
                ldsm_x4(b00, b01, b10, b11, Vc + (uint32_t)((p * 16 * FP + c * 8) * 4));
                mma_f16(acc[2*p    ], a0, a1, a2, a3, b00, b01);
                mma_f16(acc[2*p + 1], a0, a1, a2, a3, b10, b11);
            }
        }
    }

    l_lo += __shfl_xor_sync(0xffffffffu, l_lo, 1);
    l_lo += __shfl_xor_sync(0xffffffffu, l_lo, 2);
    l_hi += __shfl_xor_sync(0xffffffffu, l_hi, 1);
    l_hi += __shfl_xor_sync(0xffffffffu, l_hi, 2);

    const float inv_lo = 1.f / l_lo;
    const float inv_hi = 1.f / l_hi;
    const int b = bh / Hh, h = bh % Hh;
    __half* olo = g_o + ((size_t)b * Ss + (qr0 + g    )) * Dd + h * HDd;
    __half* ohi = g_o + ((size_t)b * Ss + (qr0 + g + 8)) * Dd + h * HDd;
    #pragma unroll
    for (int na = 0; na < 8; na++) {
        *(uint32_t*)&olo[na * 8 + tig * 2] = pack_h2(acc[na][0] * inv_lo, acc[na][1] * inv_lo);
        *(uint32_t*)&ohi[na * 8 + tig * 2] = pack_h2(acc[na][2] * inv_hi, acc[na][3] * inv_hi);
    }
}

// ---------------------------------------------------------------------------
extern "C" void kernel_launch(void* const* d_in, const int* in_sizes, int n_in,
                              void* d_out, int out_size)
{
    const float* x  = (const float*)d_in[0];
    const float* wq = (const float*)d_in[1];
    const float* bq = (const float*)d_in[2];
    const float* wk = (const float*)d_in[3];
    const float* bk = (const float*)d_in[4];
    const float* wv = (const float*)d_in[5];
    const float* bv = (const float*)d_in[6];
    const float* wo = (const float*)d_in[7];
    const float* bo = (const float*)d_in[8];
    float* out = (float*)d_out;

    cudaFuncSetAttribute(tc_gemm<true>,  cudaFuncAttributeMaxDynamicSharedMemorySize, GEMM_SMEM);
    cudaFuncSetAttribute(tc_gemm<false>, cudaFuncAttributeMaxDynamicSharedMemorySize, GEMM_SMEM);
    cudaFuncSetAttribute(flash_attn_tc,  cudaFuncAttributeMaxDynamicSharedMemorySize, FA_SMEM);

    // pre-pass: x -> fp16; weights -> transposed fp16
    round_x<<<Mm * Dd / (256 * 8), 256>>>(x);
    transpose_w<<<dim3(32, 32, 4), 256>>>(wq, wk, wv, wo);

    // fused QKV projection (fp16 tensor cores)
    dim3 qgrid(24, Mm / 128);             // (24, 64)
    tc_gemm<true><<<qgrid, 256, GEMM_SMEM>>>(bq, bk, bv, nullptr, nullptr);

    // attention
    dim3 agrid(Ss / 64, Bb * Hh);         // (32, 64)
    flash_attn_tc<<<agrid, 128, FA_SMEM>>>();

    // output projection
    dim3 ogrid(8, Mm / 128);              // (8, 64)
    tc_gemm<false><<<ogrid, 256, GEMM_SMEM>>>(nullptr, nullptr, nullptr, bo, out);
}

// round 15
// speedup vs baseline: 1.7159x; 1.0020x over previous
#include <cuda_runtime.h>
#include <cuda_fp16.h>
#include <math.h>
#include <stdint.h>

// Problem constants
#define Bb  4
#define Ss  2048
#define Dd  1024
#define Hh  16
#define HDd 64
#define Mm  (Bb*Ss)          // 8192

// Scratch (no allocation allowed -> __device__ globals). All fp16.
__device__ __align__(16) __half g_q [Bb*Hh*Ss*HDd];  // [B,H,S,HD], pre-scaled by 0.125*log2(e)
__device__ __align__(16) __half g_k [Bb*Hh*Ss*HDd];  // [B,H,S,HD]
__device__ __align__(16) __half g_vT[Bb*Hh*HDd*Ss];  // [B,H,HD,S]  (transposed!)
__device__ __align__(16) __half g_o [Bb*Ss*Dd];      // [B,S,D]
__device__ __align__(16) __half g_xt[Mm*Dd];         // x -> fp16 [M,K]
__device__ __align__(16) __half g_wt[4][Dd*Dd];      // weights TRANSPOSED [N,K], fp16

__device__ __forceinline__ uint32_t pack_h2(float lo, float hi) {
    __half2 h = __float22half2_rn(make_float2(lo, hi));
    return *(uint32_t*)&h;
}

__device__ __forceinline__ float ex2(float x) {
    float r;
    asm("ex2.approx.f32 %0, %1;" : "=f"(r) : "f"(x));
    return r;
}

__device__ __forceinline__ void mma_f16(float c[4],
                                        uint32_t a0, uint32_t a1, uint32_t a2, uint32_t a3,
                                        uint32_t b0, uint32_t b1) {
    asm volatile(
        "mma.sync.aligned.m16n8k16.row.col.f32.f16.f16.f32 "
        "{%0,%1,%2,%3}, {%4,%5,%6,%7}, {%8,%9}, {%0,%1,%2,%3};"
        : "+f"(c[0]), "+f"(c[1]), "+f"(c[2]), "+f"(c[3])
        : "r"(a0), "r"(a1), "r"(a2), "r"(a3), "r"(b0), "r"(b1));
}

__device__ __forceinline__ void ldsm_x4(uint32_t& r0, uint32_t& r1,
                                        uint32_t& r2, uint32_t& r3, uint32_t addr) {
    asm volatile("ldmatrix.sync.aligned.m8n8.x4.shared.b16 {%0,%1,%2,%3}, [%4];"
                 : "=r"(r0), "=r"(r1), "=r"(r2), "=r"(r3) : "r"(addr));
}

__device__ __forceinline__ void cp16(void* dst_smem, const void* src) {
    uint32_t d = (uint32_t)__cvta_generic_to_shared(dst_smem);
    asm volatile("cp.async.cg.shared.global [%0], [%1], 16;\n" :: "r"(d), "l"(src));
}
#define CP_COMMIT() asm volatile("cp.async.commit_group;\n" ::: "memory")
#define CP_WAIT1()  asm volatile("cp.async.wait_group 1;\n" ::: "memory")
#define CP_WAIT0()  asm volatile("cp.async.wait_group 0;\n" ::: "memory")

// ---------------------------------------------------------------------------
// Pre-pass (merged): blocks 0..4095: x (fp32) -> g_xt (fp16), 8 elems/thread.
// blocks 4096..8191: transpose + convert one 32x32 weight tile.
// ---------------------------------------------------------------------------
__global__ __launch_bounds__(256)
void prepass(const float* __restrict__ x,
             const float* __restrict__ wq, const float* __restrict__ wk,
             const float* __restrict__ wv, const float* __restrict__ wo)
{
    const int bid = blockIdx.x;
    if (bid < 4096) {
        const size_t i = ((size_t)bid * 256 + threadIdx.x) * 8;
        float4 v0 = *(const float4*)(x + i);
        float4 v1 = *(const float4*)(x + i + 4);
        uint4 u;
        u.x = pack_h2(v0.x, v0.y);  u.y = pack_h2(v0.z, v0.w);
        u.z = pack_h2(v1.x, v1.y);  u.w = pack_h2(v1.z, v1.w);
        *(uint4*)(g_xt + i) = u;
    } else {
        __shared__ float sm[32][33];
        const int t2 = bid - 4096;
        const int w = t2 >> 10;              // 0..3
        const int tile = t2 & 1023;          // 0..1023
        const int k0 = (tile & 31) * 32;
        const int n0 = (tile >> 5) * 32;
        const float* src = (w == 0) ? wq : (w == 1) ? wk : (w == 2) ? wv : wo;
        __half* dst = g_wt[w];
        const int tx = threadIdx.x & 31, ty = threadIdx.x >> 5;
        #pragma unroll
        for (int i = 0; i < 4; i++)
            sm[ty + 8 * i][tx] = src[(size_t)(k0 + ty + 8 * i) * Dd + n0 + tx];
        __syncthreads();
        #pragma unroll
        for (int i = 0; i < 4; i++)
            dst[(size_t)(n0 + ty + 8 * i) * Dd + k0 + tx] = __float2half(sm[tx][ty + 8 * i]);
    }
}

// ---------------------------------------------------------------------------
// fp16 tensor-core GEMM (m16n8k16), 3-stage cp.async ring, k-tile 64.
// [frozen from R14 — at mma.sync HMMA ceiling]
// ---------------------------------------------------------------------------
#define GP 36                      // words per smem row (k64 = 32 words + 4 pad)
#define GASTG (128*GP)             // words per A (or B) stage: 4608
#define GSTGW (2*GASTG)            // words per stage A+B: 9216 (36864 B)
#define GEMM_SMEM (3*GSTGW*4)      // 110592 bytes

#define QSCALE 0.18033688011112042f   // 0.125 * log2(e)

template<bool QKV>
__global__ __launch_bounds__(256, 2)
void tc_gemm(const float* __restrict__ bq, const float* __restrict__ bk,
             const float* __restrict__ bv, const float* __restrict__ bo,
             float* __restrict__ out_param)
{
    extern __shared__ uint32_t dsw[];

    int sel; const __half* A; const __half* W; const float* bias;
    int bnx;
    if (QKV) {
        sel = blockIdx.x >> 3;  bnx = blockIdx.x & 7;
        A = g_xt;  W = g_wt[sel];
        bias = (sel == 0) ? bq : (sel == 1) ? bk : bv;
    } else {
        sel = 3; bnx = blockIdx.x;
        A = g_o;  W = g_wt[3];  bias = bo;
    }

    const int t    = threadIdx.x;
    const int lane = t & 31;
    const int wid  = t >> 5;
    const int wm   = (wid & 3) * 32;
    const int wn   = (wid >> 2) * 64;
    const int g    = lane >> 2;
    const int tig  = lane & 3;

    const int bm = blockIdx.y * 128;
    const int bn = bnx * 128;

    const uint32_t sm0 = (uint32_t)__cvta_generic_to_shared(dsw);

    const int lrow = lane & 7;
    const int lmat = lane >> 3;
    const uint32_t lofsA = (uint32_t)((((lmat & 1) * 8 + lrow) * GP + (lmat >> 1) * 4) * 4);
    const uint32_t lofsB = (uint32_t)((((lmat >> 1) * 8 + lrow) * GP + (lmat & 1) * 4) * 4);

    const int lr = t >> 1;
    const int lcp = t & 1;
    const __half* Arow = A + (size_t)(bm + lr) * Dd + lcp * 32;
    const __half* Wrow = W + (size_t)(bn + lr) * Dd + lcp * 32;

    const int NT = Dd / 64;   // 16 k-tiles

    auto issue = [&](int kt, int stg) {
        if (kt < NT) {
            const int k0 = kt * 64;
            uint32_t* Aw = dsw + stg * GSTGW;
            uint32_t* Bw = Aw + GASTG;
            #pragma unroll
            for (int j = 0; j < 4; j++) {
                cp16(Aw + lr * GP + (lcp * 4 + j) * 4, Arow + k0 + j * 8);
                cp16(Bw + lr * GP + (lcp * 4 + j) * 4, Wrow + k0 + j * 8);
            }
        }
        CP_COMMIT();
    };

    float acc[2][8][4];
    #pragma unroll
    for (int ma = 0; ma < 2; ma++)
        #pragma unroll
        for (int na = 0; na < 8; na++)
            #pragma unroll
            for (int i = 0; i < 4; i++) acc[ma][na][i] = 0.f;

    issue(0, 0);
    issue(1, 1);

    for (int kt = 0; kt < NT; kt++) {
        const int cur = kt % 3;
        CP_WAIT1();
        __syncthreads();
        issue(kt + 2, (kt + 2) % 3);

        const uint32_t Abase = sm0 + (uint32_t)(cur * GSTGW) * 4;
        const uint32_t Bbase = Abase + (uint32_t)GASTG * 4;

        #pragma unroll
        for (int ks = 0; ks < 4; ks++) {
            const uint32_t kwo = (uint32_t)(ks * 8 * 4);
            uint32_t a[2][4];
            #pragma unroll
            for (int ma = 0; ma < 2; ma++) {
                const uint32_t ra = Abase + (uint32_t)((wm + ma * 16) * GP) * 4 + kwo + lofsA;
                ldsm_x4(a[ma][0], a[ma][1], a[ma][2], a[ma][3], ra);
            }
            #pragma unroll
            for (int p = 0; p < 4; p++) {
                uint32_t b00, b01, b10, b11;
                const uint32_t rb = Bbase + (uint32_t)((wn + p * 16) * GP) * 4 + kwo + lofsB;
                ldsm_x4(b00, b01, b10, b11, rb);
                #pragma unroll
                for (int ma = 0; ma < 2; ma++) {
                    mma_f16(acc[ma][2*p    ], a[ma][0], a[ma][1], a[ma][2], a[ma][3], b00, b01);
                    mma_f16(acc[ma][2*p + 1], a[ma][0], a[ma][1], a[ma][2], a[ma][3], b10, b11);
                }
            }
        }
    }

    #pragma unroll
    for (int ma = 0; ma < 2; ma++) {
        #pragma unroll
        for (int na = 0; na < 8; na++) {
            const int row0 = bm + wm + ma * 16 + g;
            const int col  = bn + wn + na * 8 + tig * 2;
            const float bia0 = bias[col], bia1 = bias[col + 1];
            #pragma unroll
            for (int half_i = 0; half_i < 2; half_i++) {
                const int mrow = row0 + half_i * 8;
                float v0 = acc[ma][na][half_i * 2 + 0] + bia0;
                float v1 = acc[ma][na][half_i * 2 + 1] + bia1;
                if (QKV) {
                    const int b = mrow / Ss, s = mrow % Ss;
                    const int h = col / HDd, d = col % HDd;
                    if (sel == 0) { v0 *= QSCALE; v1 *= QSCALE; }
                    if (sel == 2) {
                        __half* dst = g_vT + (((size_t)b * Hh + h) * HDd) * Ss + s;
                        dst[(size_t)d * Ss]       = __float2half(v0);
                        dst[(size_t)(d + 1) * Ss] = __float2half(v1);
                    } else {
                        __half* dst = (sel == 0) ? g_q : g_k;
                        *(uint32_t*)&dst[(((size_t)b * Hh + h) * Ss + s) * HDd + d] =
                            pack_h2(v0, v1);
                    }
                } else {
                    *(float2*)&out_param[(size_t)mrow * Dd + col] = make_float2(v0, v1);
                }
            }
        }
    }
}

// ---------------------------------------------------------------------------
// fp16 tensor-core flash attention (causal), m16n8k16, FA2-style.
// R15: heavy-first scheduling (blockIdx.x reversed) — variable-length blocks
// launch longest-first so light blocks backfill the tail wave.
// ---------------------------------------------------------------------------
#define FP 36                         // words per smem row
#define TSZ (64*FP)                   // words per tile (2304)
#define FA_SMEM (4*TSZ*4)             // K x2 + V x2 = 36864 bytes

__global__ __launch_bounds__(128)
void flash_attn_tc()
{
    extern __shared__ uint32_t dsw[];

    const int tid  = threadIdx.x;
    const int lane = tid & 31;
    const int wid  = tid >> 5;
    const int g    = lane >> 2;
    const int tig  = lane & 3;
    const int q0   = (int)(gridDim.x - 1 - blockIdx.x) * 64;   // heavy-first
    const int bh   = blockIdx.y;
    const int qr0  = q0 + wid * 16;

    const __half* qb  = g_q  + (size_t)bh * Ss * HDd;
    const __half* kb  = g_k  + (size_t)bh * Ss * HDd;
    const __half* vtb = g_vT + (size_t)bh * HDd * Ss;

    const uint32_t sm0 = (uint32_t)__cvta_generic_to_shared(dsw);

    const int lrow = lane & 7;
    const int lmat = lane >> 3;
    const uint32_t lofs = (uint32_t)((((lmat >> 1) * 8 + lrow) * FP + (lmat & 1) * 4) * 4);

    uint32_t qf[4][4];
    #pragma unroll
    for (int c = 0; c < 4; c++) {
        qf[c][0] = *(const uint32_t*)&qb[(size_t)(qr0 + g    ) * HDd + c * 16 + tig * 2    ];
        qf[c][1] = *(const uint32_t*)&qb[(size_t)(qr0 + g + 8) * HDd + c * 16 + tig * 2    ];
        qf[c][2] = *(const uint32_t*)&qb[(size_t)(qr0 + g    ) * HDd + c * 16 + tig * 2 + 8];
        qf[c][3] = *(const uint32_t*)&qb[(size_t)(qr0 + g + 8) * HDd + c * 16 + tig * 2 + 8];
    }

    float acc[8][4];
    #pragma unroll
    for (int na = 0; na < 8; na++)
        #pragma unroll
        for (int i = 0; i < 4; i++) acc[na][i] = 0.f;

    float m_lo = -INFINITY, m_hi = -INFINITY;
    float l_lo = 0.f, l_hi = 0.f;

    const int nt = q0 / 64 + 1;

    auto issue_tile = [&](int kt, int buf) {
        uint32_t* Kd = dsw + buf * TSZ;
        uint32_t* Vd = dsw + (2 + buf) * TSZ;
        #pragma unroll
        for (int i = 0; i < 4; i++) {
            const int idx = tid + i * 128;
            const int row = idx >> 3;
            const int c   = idx & 7;
            cp16(Kd + row * FP + c * 4, kb  + (size_t)(kt * 64 + row) * HDd + c * 8);
            cp16(Vd + row * FP + c * 4, vtb + (size_t)row * Ss + kt * 64 + c * 8);
        }
        CP_COMMIT();
    };

    issue_tile(0, 0);

    for (int kt = 0; kt < nt; kt++) {
        const int cur = kt & 1;
        CP_WAIT0();
        __syncthreads();
        if (kt + 1 < nt) issue_tile(kt + 1, cur ^ 1);

        const uint32_t Kc = sm0 + (uint32_t)(cur * TSZ) * 4 + lofs;
        const uint32_t Vc = sm0 + (uint32_t)((2 + cur) * TSZ) * 4 + lofs;

        float s[8][4];
        #pragma unroll
        for (int na = 0; na < 8; na++)
            #pragma unroll
            for (int i = 0; i < 4; i++) s[na][i] = 0.f;

        #pragma unroll
        for (int c = 0; c < 4; c++) {
            #pragma unroll
            for (int p = 0; p < 4; p++) {
                uint32_t b00, b01, b10, b11;
                ldsm_x4(b00, b01, b10, b11, Kc + (uint32_t)((p * 16 * FP + c * 8) * 4));
                mma_f16(s[2*p    ], qf[c][0], qf[c][1], qf[c][2], qf[c][3], b00, b01);
                mma_f16(s[2*p + 1], qf[c][0], qf[c][1], qf[c][2], qf[c][3], b10, b11);
            }
        }

        if (kt == nt - 1) {
            const int rlo = qr0 + g, rhi = qr0 + g + 8;
            #pragma unroll
            for (int na = 0; na < 8; na++) {
                const int c0 = kt * 64 + na * 8 + tig * 2;
                const int c1 = c0 + 1;
                if (c0 > rlo) s[na][0] = -INFINITY;
                if (c1 > rlo) s[na][1] = -INFINITY;
                if (c0 > rhi) s[na][2] = -INFINITY;
                if (c1 > rhi) s[na][3] = -INFINITY;
            }
        }

        float tm_lo = -INFINITY, tm_hi = -INFINITY;
        #pragma unroll
        for (int na = 0; na < 8; na++) {
            tm_lo = fmaxf(tm_lo, fmaxf(s[na][0], s[na][1]));
            tm_hi = fmaxf(tm_hi, fmaxf(s[na][2], s[na][3]));
        }
        tm_lo = fmaxf(tm_lo, __shfl_xor_sync(0xffffffffu, tm_lo, 1));
        tm_lo = fmaxf(tm_lo, __shfl_xor_sync(0xffffffffu, tm_lo, 2));
        tm_hi = fmaxf(tm_hi, __shfl_xor_sync(0xffffffffu, tm_hi, 1));
        tm_hi = fmaxf(tm_hi, __shfl_xor_sync(0xffffffffu, tm_hi, 2));

        const float mn_lo = fmaxf(m_lo, tm_lo);
        const float mn_hi = fmaxf(m_hi, tm_hi);
        const float sc_lo = ex2(m_lo - mn_lo);
        const float sc_hi = ex2(m_hi - mn_hi);
        m_lo = mn_lo;  m_hi = mn_hi;

        float sum_lo = 0.f, sum_hi = 0.f;
        #pragma unroll
        for (int na = 0; na < 8; na++) {
            s[na][0] = ex2(s[na][0] - mn_lo);
            s[na][1] = ex2(s[na][1] - mn_lo);
            s[na][2] = ex2(s[na][2] - mn_hi);
            s[na][3] = ex2(s[na][3] - mn_hi);
            sum_lo += s[na][0] + s[na][1];
            sum_hi += s[na][2] + s[na][3];
        }
        l_lo = l_lo * sc_lo + sum_lo;
        l_hi = l_hi * sc_hi + sum_hi;

        #pragma unroll
        for (int na = 0; na < 8; na++) {
            acc[na][0] *= sc_lo; acc[na][1] *= sc_lo;
            acc[na][2] *= sc_hi; acc[na][3] *= sc_hi;
        }

        #pragma unroll
        for (int c = 0; c < 4; c++) {
            const uint32_t a0 = pack_h2(s[2 * c    ][0], s[2 * c    ][1]);
            const uint32_t a1 = pack_h2(s[2 * c    ][2], s[2 * c    ][3]);
            const uint32_t a2 = pack_h2(s[2 * c + 1][0], s[2 * c + 1][1]);
            const uint32_t a3 = pack_h2(s[2 * c + 1][2], s[2 * c + 1][3]);
            #pragma unroll
            for (int p = 0; p < 4; p++) {
                uint32_t b00, b01, b10, b11;
                ldsm_x4(b00, b01, b10, b11, Vc + (uint32_t)((p * 16 * FP + c * 8) * 4));
                mma_f16(acc[2*p    ], a0, a1, a2, a3, b00, b01);
                mma_f16(acc[2*p + 1], a0, a1, a2, a3, b10, b11);
            }
        }
    }

    l_lo += __shfl_xor_sync(0xffffffffu, l_lo, 1);
    l_lo += __shfl_xor_sync(0xffffffffu, l_lo, 2);
    l_hi += __shfl_xor_sync(0xffffffffu, l_hi, 1);
    l_hi += __shfl_xor_sync(0xffffffffu, l_hi, 2);

    const float inv_lo = 1.f / l_lo;
    const float inv_hi = 1.f / l_hi;
    const int b = bh / Hh, h = bh % Hh;
    __half* olo = g_o + ((size_t)b * Ss + (qr0 + g    )) * Dd + h * HDd;
    __half* ohi = g_o + ((size_t)b * Ss + (qr0 + g + 8)) * Dd + h * HDd;
    #pragma unroll
    for (int na = 0; na < 8; na++) {
        *(uint32_t*)&olo[na * 8 + tig * 2] = pack_h2(acc[na][0] * inv_lo, acc[na][1] * inv_lo);
        *(uint32_t*)&ohi[na * 8 + tig * 2] = pack_h2(acc[na][2] * inv_hi, acc[na][3] * inv_hi);
    }
}

// ---------------------------------------------------------------------------
extern "C" void kernel_launch(void* const* d_in, const int* in_sizes, int n_in,
                              void* d_out, int out_size)
{
    const float* x  = (const float*)d_in[0];
    const float* wq = (const float*)d_in[1];
    const float* bq = (const float*)d_in[2];
    const float* wk = (const float*)d_in[3];
    const float* bk = (const float*)d_in[4];
    const float* wv = (const float*)d_in[5];
    const float* bv = (const float*)d_in[6];
    const float* wo = (const float*)d_in[7];
    const float* bo = (const float*)d_in[8];
    float* out = (float*)d_out;

    cudaFuncSetAttribute(tc_gemm<true>,  cudaFuncAttributeMaxDynamicSharedMemorySize, GEMM_SMEM);
    cudaFuncSetAttribute(tc_gemm<false>, cudaFuncAttributeMaxDynamicSharedMemorySize, GEMM_SMEM);
    cudaFuncSetAttribute(flash_attn_tc,  cudaFuncAttributeMaxDynamicSharedMemorySize, FA_SMEM);

    // merged pre-pass: x -> fp16 (blocks 0..4095); weights transpose (4096..8191)
    prepass<<<8192, 256>>>(x, wq, wk, wv, wo);

    // fused QKV projection (fp16 tensor cores)
    dim3 qgrid(24, Mm / 128);             // (24, 64)
    tc_gemm<true><<<qgrid, 256, GEMM_SMEM>>>(bq, bk, bv, nullptr, nullptr);

    // attention (heavy-first)
    dim3 agrid(Ss / 64, Bb * Hh);         // (32, 64)
    flash_attn_tc<<<agrid, 128, FA_SMEM>>>();

    // output projection
    dim3 ogrid(8, Mm / 128);              // (8, 64)
    tc_gemm<false><<<ogrid, 256, GEMM_SMEM>>>(nullptr, nullptr, nullptr, bo, out);
}